// round 1
// baseline (speedup 1.0000x reference)
#include <cuda_runtime.h>
#include <cuda_bf16.h>

// ---------------- problem dims ----------------
#define BB   8
#define LL   1024
#define DDIM 512
#define HH   8
#define EE   64
#define DFF  2048
#define NBLK 3

#define BLD  (BB*LL*DDIM)        // 4194304
#define BLL  (BB*LL*LL)          // 8388608
#define BHLL (BB*HH*LL*LL)       // 67108864
#define BLDF (BB*LL*DFF)         // 16777216

// ---------------- scratch (device globals; no allocs allowed) ----------------
__device__ float g_q[BLD];
__device__ float g_k[BLD];
__device__ float g_v[BLD];
__device__ float g_t[BLD];
__device__ float g_t2[BLD];
__device__ float g_x[BLD];
__device__ float g_y[BLD];
__device__ float g_xn[BLD];
__device__ float g_s[BLL];
__device__ float g_h[BLDF];
__device__ float g_A[BHLL];     // fallback if d_out has no room for A

// ---------------- SGEMM: C = alpha * A@op(B) [+bias] [+res] [relu] ----------------
// Tiles 64x64, BK=16, 256 threads, 4x4 per thread. All dims multiples of 64/16.
template<bool TB, bool RELU>
__global__ void sgemm_kernel(const float* __restrict__ A, const float* __restrict__ B,
                             float* __restrict__ C,
                             const float* __restrict__ bias,
                             const float* __restrict__ res,
                             int K, int lda, int ldb, int ldc,
                             float alpha, int inner,
                             long long sAo, long long sAi,
                             long long sBo, long long sBi,
                             long long sCo, long long sCi)
{
    int z  = blockIdx.z;
    int zo = z / inner;
    int zi = z - zo * inner;
    A += zo * sAo + zi * sAi;
    B += zo * sBo + zi * sBi;
    long long coff = zo * sCo + zi * sCi;
    C += coff;
    if (res) res += coff;

    __shared__ float As[16][64];
    __shared__ float Bs[16][64];

    int tid = threadIdx.x;
    int tx = tid & 15, ty = tid >> 4;
    int row0 = blockIdx.y * 64;
    int col0 = blockIdx.x * 64;

    float acc[4][4] = {};

    for (int k0 = 0; k0 < K; k0 += 16) {
        #pragma unroll
        for (int i = 0; i < 4; i++) {
            int idx = tid + i * 256;
            int m = idx >> 4, kk = idx & 15;
            As[kk][m] = A[(long long)(row0 + m) * lda + (k0 + kk)];
        }
        #pragma unroll
        for (int i = 0; i < 4; i++) {
            int idx = tid + i * 256;
            if (TB) {
                int n = idx >> 4, kk = idx & 15;
                Bs[kk][n] = B[(long long)(col0 + n) * ldb + (k0 + kk)];
            } else {
                int kk = idx >> 6, n = idx & 63;
                Bs[kk][n] = B[(long long)(k0 + kk) * ldb + (col0 + n)];
            }
        }
        __syncthreads();
        #pragma unroll
        for (int kk = 0; kk < 16; kk++) {
            float a[4], bv[4];
            #pragma unroll
            for (int i = 0; i < 4; i++) a[i]  = As[kk][ty * 4 + i];
            #pragma unroll
            for (int j = 0; j < 4; j++) bv[j] = Bs[kk][tx * 4 + j];
            #pragma unroll
            for (int i = 0; i < 4; i++)
                #pragma unroll
                for (int j = 0; j < 4; j++)
                    acc[i][j] += a[i] * bv[j];
        }
        __syncthreads();
    }

    #pragma unroll
    for (int i = 0; i < 4; i++) {
        int m = row0 + ty * 4 + i;
        #pragma unroll
        for (int j = 0; j < 4; j++) {
            int n = col0 + tx * 4 + j;
            float v = acc[i][j] * alpha;
            if (bias) v += bias[n];
            if (res)  v += res[(long long)m * ldc + n];
            if (RELU) v = v > 0.f ? v : 0.f;
            C[(long long)m * ldc + n] = v;
        }
    }
}

// ---------------- row softmax, row length 1024, 256 threads ----------------
__global__ void softmax_kernel(float* __restrict__ P)
{
    long long base = (long long)blockIdx.x * 1024;
    int tid = threadIdx.x;
    __shared__ float red[256];

    float v[4];
    float mx = -3.4e38f;
    #pragma unroll
    for (int i = 0; i < 4; i++) {
        v[i] = P[base + tid + i * 256];
        mx = fmaxf(mx, v[i]);
    }
    red[tid] = mx; __syncthreads();
    for (int s = 128; s > 0; s >>= 1) {
        if (tid < s) red[tid] = fmaxf(red[tid], red[tid + s]);
        __syncthreads();
    }
    mx = red[0]; __syncthreads();

    float sum = 0.f;
    #pragma unroll
    for (int i = 0; i < 4; i++) {
        v[i] = expf(v[i] - mx);
        sum += v[i];
    }
    red[tid] = sum; __syncthreads();
    for (int s = 128; s > 0; s >>= 1) {
        if (tid < s) red[tid] += red[tid + s];
        __syncthreads();
    }
    float inv = 1.f / red[0];
    #pragma unroll
    for (int i = 0; i < 4; i++)
        P[base + tid + i * 256] = v[i] * inv;
}

// ---------------- layernorm over D=512; input = a (+ b if b!=null) ----------------
__global__ void ln_kernel(const float* __restrict__ a, const float* __restrict__ b,
                          const float* __restrict__ g, const float* __restrict__ beta,
                          float* __restrict__ out)
{
    long long base = (long long)blockIdx.x * 512;
    int tid = threadIdx.x;   // 256
    __shared__ float red[256];

    float x0 = a[base + tid];
    float x1 = a[base + tid + 256];
    if (b) { x0 += b[base + tid]; x1 += b[base + tid + 256]; }

    red[tid] = x0 + x1; __syncthreads();
    for (int s = 128; s > 0; s >>= 1) {
        if (tid < s) red[tid] += red[tid + s];
        __syncthreads();
    }
    float mean = red[0] * (1.f / 512.f);
    __syncthreads();

    float d0 = x0 - mean, d1 = x1 - mean;
    red[tid] = d0 * d0 + d1 * d1; __syncthreads();
    for (int s = 128; s > 0; s >>= 1) {
        if (tid < s) red[tid] += red[tid + s];
        __syncthreads();
    }
    float rstd = rsqrtf(red[0] * (1.f / 512.f) + 1e-5f);

    out[base + tid]       = d0 * rstd * g[tid]       + beta[tid];
    out[base + tid + 256] = d1 * rstd * g[tid + 256] + beta[tid + 256];
}

// ---------------- temporal "transpose-reshape": out[b, f] = in[b, (f%L)*D + f/L] ----------------
__global__ void permute_kernel(const float* __restrict__ in, float* __restrict__ out)
{
    long long i = (long long)blockIdx.x * 256 + threadIdx.x;
    if (i >= (long long)BLD) return;
    long long bidx = i / (LL * DDIM);
    int f = (int)(i - bidx * (LL * DDIM));
    out[i] = in[bidx * (LL * DDIM) + (long long)(f & (LL - 1)) * DDIM + (f >> 10)];
}

// ---------------- host-side helpers ----------------
static void sgemm(const float* A, const float* B, float* C,
                  const float* bias, const float* res,
                  int M, int N, int K, int lda, int ldb, int ldc,
                  float alpha, bool tb, bool relu,
                  int batch, int inner,
                  long long sAo, long long sAi,
                  long long sBo, long long sBi,
                  long long sCo, long long sCi)
{
    dim3 grid(N / 64, M / 64, batch);
    if (tb) {
        if (relu) sgemm_kernel<true , true ><<<grid, 256>>>(A, B, C, bias, res, K, lda, ldb, ldc, alpha, inner, sAo, sAi, sBo, sBi, sCo, sCi);
        else      sgemm_kernel<true , false><<<grid, 256>>>(A, B, C, bias, res, K, lda, ldb, ldc, alpha, inner, sAo, sAi, sBo, sBi, sCo, sCi);
    } else {
        if (relu) sgemm_kernel<false, true ><<<grid, 256>>>(A, B, C, bias, res, K, lda, ldb, ldc, alpha, inner, sAo, sAi, sBo, sBi, sCo, sCi);
        else      sgemm_kernel<false, false><<<grid, 256>>>(A, B, C, bias, res, K, lda, ldb, ldc, alpha, inner, sAo, sAi, sBo, sBi, sCo, sCi);
    }
}

extern "C" void kernel_launch(void* const* d_in, const int* in_sizes, int n_in,
                              void* d_out, int out_size)
{
    // inputs per metadata order
    const float* x0   = (const float*)d_in[0];
    const float* aw_q = (const float*)d_in[1];   const float* ab_q = (const float*)d_in[2];
    const float* aw_k = (const float*)d_in[3];   const float* ab_k = (const float*)d_in[4];
    const float* aw_v = (const float*)d_in[5];   const float* ab_v = (const float*)d_in[6];
    const float* aw_o = (const float*)d_in[7];   const float* ab_o = (const float*)d_in[8];
    const float* n1g  = (const float*)d_in[9];   const float* n1b  = (const float*)d_in[10];
    const float* n2g  = (const float*)d_in[11];  const float* n2b  = (const float*)d_in[12];
    const float* tqw  = (const float*)d_in[13];  const float* tqb  = (const float*)d_in[14];
    const float* tkw  = (const float*)d_in[15];  const float* tkb  = (const float*)d_in[16];
    const float* tvw  = (const float*)d_in[17];  const float* tvb  = (const float*)d_in[18];
    const float* tow  = (const float*)d_in[19];  const float* tob  = (const float*)d_in[20];
    const float* tf1w = (const float*)d_in[21];  const float* tf1b = (const float*)d_in[22];
    const float* tf2w = (const float*)d_in[23];  const float* tf2b = (const float*)d_in[24];
    const float* tng  = (const float*)d_in[25];  const float* tnb  = (const float*)d_in[26];

    float *q, *k, *v, *t, *t2, *x, *y, *xn, *s, *h, *Afb;
    cudaGetSymbolAddress((void**)&q,  g_q);
    cudaGetSymbolAddress((void**)&k,  g_k);
    cudaGetSymbolAddress((void**)&v,  g_v);
    cudaGetSymbolAddress((void**)&t,  g_t);
    cudaGetSymbolAddress((void**)&t2, g_t2);
    cudaGetSymbolAddress((void**)&x,  g_x);
    cudaGetSymbolAddress((void**)&y,  g_y);
    cudaGetSymbolAddress((void**)&xn, g_xn);
    cudaGetSymbolAddress((void**)&s,  g_s);
    cudaGetSymbolAddress((void**)&h,  g_h);
    cudaGetSymbolAddress((void**)&Afb, g_A);

    float* out_ln = (float*)d_out;
    float* Ap = (out_size >= (BLD + BHLL)) ? ((float*)d_out + BLD) : Afb;

    const int M = BB * LL;       // 8192
    const long long LD = (long long)LL * DDIM;
    const long long LLs = (long long)LL * LL;

    // ---- outer multi-head attention ----
    sgemm(x0, aw_q, q, ab_q, nullptr, M, DDIM, DDIM, DDIM, DDIM, DDIM, 1.f, false, false, 1, 1, 0,0,0,0,0,0);
    sgemm(x0, aw_k, k, ab_k, nullptr, M, DDIM, DDIM, DDIM, DDIM, DDIM, 1.f, false, false, 1, 1, 0,0,0,0,0,0);
    sgemm(x0, aw_v, v, ab_v, nullptr, M, DDIM, DDIM, DDIM, DDIM, DDIM, 1.f, false, false, 1, 1, 0,0,0,0,0,0);

    // scores[b,h] = q_h @ k_h^T / 8  -> Ap  (batch = B*H, inner = H)
    sgemm(q, k, Ap, nullptr, nullptr, LL, LL, EE, DDIM, DDIM, LL, 0.125f, true, false,
          BB * HH, HH, LD, EE, LD, EE, (long long)HH * LLs, LLs);
    softmax_kernel<<<BB * HH * LL, 256>>>(Ap);

    // out = A @ v_h  -> t   (ldc=512, head offset 64)
    sgemm(Ap, v, t, nullptr, nullptr, LL, EE, LL, LL, DDIM, DDIM, 1.f, false, false,
          BB * HH, HH, (long long)HH * LLs, LLs, LD, EE, LD, EE);

    // t2 = t @ aw_o + ab_o + x0 ; x = LN(t2)
    sgemm(t, aw_o, t2, ab_o, x0, M, DDIM, DDIM, DDIM, DDIM, DDIM, 1.f, false, false, 1, 1, 0,0,0,0,0,0);
    ln_kernel<<<M, 256>>>(t2, nullptr, n1g, n1b, x);

    // y = x
    cudaMemcpyAsync(y, x, (size_t)BLD * sizeof(float), cudaMemcpyDeviceToDevice, 0);

    // ---- 3 temporal blocks ----
    for (int i = 0; i < NBLK; i++) {
        const float* Wq = tqw + (long long)i * DDIM * DDIM;  const float* bq = tqb + i * DDIM;
        const float* Wk = tkw + (long long)i * DDIM * DDIM;  const float* bk = tkb + i * DDIM;
        const float* Wv = tvw + (long long)i * DDIM * DDIM;  const float* bv = tvb + i * DDIM;
        const float* Wo = tow + (long long)i * DDIM * DDIM;  const float* bo = tob + i * DDIM;
        const float* W1 = tf1w + (long long)i * DDIM * DFF;  const float* b1 = tf1b + i * DFF;
        const float* W2 = tf2w + (long long)i * DFF * DDIM;  const float* b2 = tf2b + i * DDIM;
        const float* ng = tng + i * DDIM;                    const float* nb = tnb + i * DDIM;

        sgemm(y, Wq, q, bq, nullptr, M, DDIM, DDIM, DDIM, DDIM, DDIM, 1.f, false, false, 1, 1, 0,0,0,0,0,0);
        sgemm(y, Wk, k, bk, nullptr, M, DDIM, DDIM, DDIM, DDIM, DDIM, 1.f, false, false, 1, 1, 0,0,0,0,0,0);
        sgemm(y, Wv, v, bv, nullptr, M, DDIM, DDIM, DDIM, DDIM, DDIM, 1.f, false, false, 1, 1, 0,0,0,0,0,0);

        // scores[b] = q @ k^T (no scaling), batch = B
        sgemm(q, k, s, nullptr, nullptr, LL, LL, DDIM, DDIM, DDIM, LL, 1.f, true, false,
              BB, 1, LD, 0, LD, 0, LLs, 0);
        softmax_kernel<<<BB * LL, 256>>>(s);

        // out = probs @ v, batch = B
        sgemm(s, v, t, nullptr, nullptr, LL, DDIM, LL, LL, DDIM, DDIM, 1.f, false, false,
              BB, 1, LLs, 0, LD, 0, LD, 0);

        // transpose-reshape reinterpret
        permute_kernel<<<(BLD + 255) / 256, 256>>>(t, t2);

        // y = y + t2 @ Wo + bo
        sgemm(t2, Wo, y, bo, y, M, DDIM, DDIM, DDIM, DDIM, DDIM, 1.f, false, false, 1, 1, 0,0,0,0,0,0);

        // xn = LN(y); h = relu(xn@W1+b1); y = y + h@W2+b2
        ln_kernel<<<M, 256>>>(y, nullptr, ng, nb, xn);
        sgemm(xn, W1, h, b1, nullptr, M, DFF, DDIM, DDIM, DFF, DFF, 1.f, false, true, 1, 1, 0,0,0,0,0,0);
        sgemm(h,  W2, y, b2, y,       M, DDIM, DFF,  DFF,  DDIM, DDIM, 1.f, false, false, 1, 1, 0,0,0,0,0,0);
    }

    // ---- final: out = LN(x + y) ----
    ln_kernel<<<M, 256>>>(x, y, n2g, n2b, out_ln);
}

// round 2
// speedup vs baseline: 2.5656x; 2.5656x over previous
#include <cuda_runtime.h>
#include <cuda_bf16.h>

// ---------------- problem dims ----------------
#define BB   8
#define LL   1024
#define DDIM 512
#define HH   8
#define EE   64
#define DFF  2048
#define NBLK 3

#define BLD  (BB*LL*DDIM)        // 4194304
#define BLL  (BB*LL*LL)          // 8388608
#define BHLL (BB*HH*LL*LL)       // 67108864
#define BLDF (BB*LL*DFF)         // 16777216

// ---------------- scratch (device globals; no allocs allowed) ----------------
__device__ float g_q[BLD];
__device__ float g_k[BLD];
__device__ float g_v[BLD];
__device__ float g_t[BLD];
__device__ float g_t2[BLD];
__device__ float g_x[BLD];
__device__ float g_y[BLD];
__device__ float g_xn[BLD];
__device__ float g_s[BLL];
__device__ float g_h[BLDF];
__device__ float g_A[BHLL];     // fallback if d_out has no room for A

// ================= SGEMM v2: C = alpha * A@op(B) [+bias] [+res] [relu] =================
// BMxBN tile, BK=16, 256 threads, TMxTN per thread, float4 LDS/LDG/STG.
// As/Bs stored K-major with +4 padding (16B-aligned rows, low STS conflicts).
template<int BM, int BN, int TM, int TN, bool TB, bool RELU>
__global__ void __launch_bounds__(256) gemm_kernel(
    const float* __restrict__ A, const float* __restrict__ B,
    float* __restrict__ C,
    const float* __restrict__ bias,
    const float* __restrict__ res,
    int K, int lda, int ldb, int ldc,
    float alpha, int inner,
    long long sAo, long long sAi,
    long long sBo, long long sBi,
    long long sCo, long long sCi)
{
    int z  = blockIdx.z;
    int zo = z / inner;
    int zi = z - zo * inner;
    A += zo * sAo + zi * sAi;
    B += zo * sBo + zi * sBi;
    long long coff = zo * sCo + zi * sCi;
    C += coff;
    if (res) res += coff;

    __shared__ float As[16][BM + 4];
    __shared__ float Bs[16][BN + 4];

    const int tid  = threadIdx.x;
    const int NT   = BN / TN;              // threads along N
    const int tx   = tid % NT;
    const int ty   = tid / NT;
    const int row0 = blockIdx.y * BM;
    const int col0 = blockIdx.x * BN;

    float acc[TM][TN];
    #pragma unroll
    for (int i = 0; i < TM; i++)
        #pragma unroll
        for (int j = 0; j < TN; j++) acc[i][j] = 0.f;

    for (int k0 = 0; k0 < K; k0 += 16) {
        // ---- load A tile (BM x 16), transpose into As[k][m] ----
        #pragma unroll
        for (int i = 0; i < (BM * 16) / (256 * 4); i++) {
            int f  = tid + i * 256;        // float4 index
            int m  = f >> 2;
            int kq = f & 3;
            float4 vv = *(const float4*)&A[(size_t)(row0 + m) * lda + k0 + kq * 4];
            As[kq * 4 + 0][m] = vv.x;
            As[kq * 4 + 1][m] = vv.y;
            As[kq * 4 + 2][m] = vv.z;
            As[kq * 4 + 3][m] = vv.w;
        }
        // ---- load B tile ----
        if (TB) {
            // B is [N,K]: load float4 along K, transpose into Bs[k][n]
            #pragma unroll
            for (int i = 0; i < (BN * 16) / (256 * 4); i++) {
                int f  = tid + i * 256;
                int n  = f >> 2;
                int kq = f & 3;
                float4 vv = *(const float4*)&B[(size_t)(col0 + n) * ldb + k0 + kq * 4];
                Bs[kq * 4 + 0][n] = vv.x;
                Bs[kq * 4 + 1][n] = vv.y;
                Bs[kq * 4 + 2][n] = vv.z;
                Bs[kq * 4 + 3][n] = vv.w;
            }
        } else {
            // B is [K,N]: load float4 along N, store rows directly
            #pragma unroll
            for (int i = 0; i < (BN * 16) / (256 * 4); i++) {
                int f  = tid + i * 256;
                int k  = f / (BN / 4);
                int nq = f % (BN / 4);
                float4 vv = *(const float4*)&B[(size_t)(k0 + k) * ldb + col0 + nq * 4];
                *(float4*)&Bs[k][nq * 4] = vv;
            }
        }
        __syncthreads();

        // ---- compute ----
        #pragma unroll
        for (int kk = 0; kk < 16; kk++) {
            float a[TM], b[TN];
            #pragma unroll
            for (int i = 0; i < TM / 4; i++)
                *(float4*)&a[i * 4] = *(const float4*)&As[kk][ty * TM + i * 4];
            #pragma unroll
            for (int j = 0; j < TN / 4; j++)
                *(float4*)&b[j * 4] = *(const float4*)&Bs[kk][tx * TN + j * 4];
            #pragma unroll
            for (int i = 0; i < TM; i++)
                #pragma unroll
                for (int j = 0; j < TN; j++)
                    acc[i][j] += a[i] * b[j];
        }
        __syncthreads();
    }

    // ---- epilogue: float4 stores ----
    #pragma unroll
    for (int i = 0; i < TM; i++) {
        int m = row0 + ty * TM + i;
        #pragma unroll
        for (int j4 = 0; j4 < TN / 4; j4++) {
            int n = col0 + tx * TN + j4 * 4;
            float4 vv;
            vv.x = acc[i][j4 * 4 + 0] * alpha;
            vv.y = acc[i][j4 * 4 + 1] * alpha;
            vv.z = acc[i][j4 * 4 + 2] * alpha;
            vv.w = acc[i][j4 * 4 + 3] * alpha;
            if (bias) {
                float4 bb = *(const float4*)&bias[n];
                vv.x += bb.x; vv.y += bb.y; vv.z += bb.z; vv.w += bb.w;
            }
            if (res) {
                float4 rr = *(const float4*)&res[(size_t)m * ldc + n];
                vv.x += rr.x; vv.y += rr.y; vv.z += rr.z; vv.w += rr.w;
            }
            if (RELU) {
                vv.x = fmaxf(vv.x, 0.f); vv.y = fmaxf(vv.y, 0.f);
                vv.z = fmaxf(vv.z, 0.f); vv.w = fmaxf(vv.w, 0.f);
            }
            *(float4*)&C[(size_t)m * ldc + n] = vv;
        }
    }
}

// ---------------- row softmax, row length 1024, 256 threads ----------------
__global__ void softmax_kernel(float* __restrict__ P)
{
    long long base = (long long)blockIdx.x * 1024;
    int tid = threadIdx.x;
    __shared__ float red[256];

    float4 vv = *(const float4*)&P[base + tid * 4];
    float v[4] = {vv.x, vv.y, vv.z, vv.w};
    float mx = fmaxf(fmaxf(v[0], v[1]), fmaxf(v[2], v[3]));
    red[tid] = mx; __syncthreads();
    for (int s = 128; s > 0; s >>= 1) {
        if (tid < s) red[tid] = fmaxf(red[tid], red[tid + s]);
        __syncthreads();
    }
    mx = red[0]; __syncthreads();

    float sum = 0.f;
    #pragma unroll
    for (int i = 0; i < 4; i++) { v[i] = __expf(v[i] - mx); sum += v[i]; }
    red[tid] = sum; __syncthreads();
    for (int s = 128; s > 0; s >>= 1) {
        if (tid < s) red[tid] += red[tid + s];
        __syncthreads();
    }
    float inv = 1.f / red[0];
    vv.x = v[0] * inv; vv.y = v[1] * inv; vv.z = v[2] * inv; vv.w = v[3] * inv;
    *(float4*)&P[base + tid * 4] = vv;
}

// ---------------- layernorm over D=512; input = a (+ b if b!=null) ----------------
__global__ void ln_kernel(const float* __restrict__ a, const float* __restrict__ b,
                          const float* __restrict__ g, const float* __restrict__ beta,
                          float* __restrict__ out)
{
    long long base = (long long)blockIdx.x * 512;
    int tid = threadIdx.x;   // 128 threads, 4 floats each
    __shared__ float red[128];

    float4 xv = *(const float4*)&a[base + tid * 4];
    if (b) {
        float4 bv = *(const float4*)&b[base + tid * 4];
        xv.x += bv.x; xv.y += bv.y; xv.z += bv.z; xv.w += bv.w;
    }

    red[tid] = xv.x + xv.y + xv.z + xv.w; __syncthreads();
    for (int s = 64; s > 0; s >>= 1) {
        if (tid < s) red[tid] += red[tid + s];
        __syncthreads();
    }
    float mean = red[0] * (1.f / 512.f);
    __syncthreads();

    float d0 = xv.x - mean, d1 = xv.y - mean, d2 = xv.z - mean, d3 = xv.w - mean;
    red[tid] = d0 * d0 + d1 * d1 + d2 * d2 + d3 * d3; __syncthreads();
    for (int s = 64; s > 0; s >>= 1) {
        if (tid < s) red[tid] += red[tid + s];
        __syncthreads();
    }
    float rstd = rsqrtf(red[0] * (1.f / 512.f) + 1e-5f);

    float4 gv = *(const float4*)&g[tid * 4];
    float4 bt = *(const float4*)&beta[tid * 4];
    float4 ov;
    ov.x = d0 * rstd * gv.x + bt.x;
    ov.y = d1 * rstd * gv.y + bt.y;
    ov.z = d2 * rstd * gv.z + bt.z;
    ov.w = d3 * rstd * gv.w + bt.w;
    *(float4*)&out[base + tid * 4] = ov;
}

// ---------------- temporal "transpose-reshape": out[b, f] = in[b, (f%L)*D + f/L] ----------------
__global__ void permute_kernel(const float* __restrict__ in, float* __restrict__ out)
{
    long long i = (long long)blockIdx.x * 256 + threadIdx.x;
    if (i >= (long long)BLD) return;
    long long bidx = i / (LL * DDIM);
    int f = (int)(i - bidx * (LL * DDIM));
    out[i] = in[bidx * (LL * DDIM) + (long long)(f & (LL - 1)) * DDIM + (f >> 10)];
}

// ---------------- host-side dispatch ----------------
static void sgemm(const float* A, const float* B, float* C,
                  const float* bias, const float* res,
                  int M, int N, int K, int lda, int ldb, int ldc,
                  float alpha, bool tb, bool relu,
                  int batch, int inner,
                  long long sAo, long long sAi,
                  long long sBo, long long sBi,
                  long long sCo, long long sCi)
{
    if (N % 128 == 0) {
        dim3 grid(N / 128, M / 128, batch);
        if (tb) {
            if (relu) gemm_kernel<128,128,8,8,true ,true ><<<grid,256>>>(A,B,C,bias,res,K,lda,ldb,ldc,alpha,inner,sAo,sAi,sBo,sBi,sCo,sCi);
            else      gemm_kernel<128,128,8,8,true ,false><<<grid,256>>>(A,B,C,bias,res,K,lda,ldb,ldc,alpha,inner,sAo,sAi,sBo,sBi,sCo,sCi);
        } else {
            if (relu) gemm_kernel<128,128,8,8,false,true ><<<grid,256>>>(A,B,C,bias,res,K,lda,ldb,ldc,alpha,inner,sAo,sAi,sBo,sBi,sCo,sCi);
            else      gemm_kernel<128,128,8,8,false,false><<<grid,256>>>(A,B,C,bias,res,K,lda,ldb,ldc,alpha,inner,sAo,sAi,sBo,sBi,sCo,sCi);
        }
    } else {
        // N multiple of 64 (the head-sliced A@V GEMM)
        dim3 grid(N / 64, M / 128, batch);
        if (tb) {
            if (relu) gemm_kernel<128,64,8,4,true ,true ><<<grid,256>>>(A,B,C,bias,res,K,lda,ldb,ldc,alpha,inner,sAo,sAi,sBo,sBi,sCo,sCi);
            else      gemm_kernel<128,64,8,4,true ,false><<<grid,256>>>(A,B,C,bias,res,K,lda,ldb,ldc,alpha,inner,sAo,sAi,sBo,sBi,sCo,sCi);
        } else {
            if (relu) gemm_kernel<128,64,8,4,false,true ><<<grid,256>>>(A,B,C,bias,res,K,lda,ldb,ldc,alpha,inner,sAo,sAi,sBo,sBi,sCo,sCi);
            else      gemm_kernel<128,64,8,4,false,false><<<grid,256>>>(A,B,C,bias,res,K,lda,ldb,ldc,alpha,inner,sAo,sAi,sBo,sBi,sCo,sCi);
        }
    }
}

extern "C" void kernel_launch(void* const* d_in, const int* in_sizes, int n_in,
                              void* d_out, int out_size)
{
    const float* x0   = (const float*)d_in[0];
    const float* aw_q = (const float*)d_in[1];   const float* ab_q = (const float*)d_in[2];
    const float* aw_k = (const float*)d_in[3];   const float* ab_k = (const float*)d_in[4];
    const float* aw_v = (const float*)d_in[5];   const float* ab_v = (const float*)d_in[6];
    const float* aw_o = (const float*)d_in[7];   const float* ab_o = (const float*)d_in[8];
    const float* n1g  = (const float*)d_in[9];   const float* n1b  = (const float*)d_in[10];
    const float* n2g  = (const float*)d_in[11];  const float* n2b  = (const float*)d_in[12];
    const float* tqw  = (const float*)d_in[13];  const float* tqb  = (const float*)d_in[14];
    const float* tkw  = (const float*)d_in[15];  const float* tkb  = (const float*)d_in[16];
    const float* tvw  = (const float*)d_in[17];  const float* tvb  = (const float*)d_in[18];
    const float* tow  = (const float*)d_in[19];  const float* tob  = (const float*)d_in[20];
    const float* tf1w = (const float*)d_in[21];  const float* tf1b = (const float*)d_in[22];
    const float* tf2w = (const float*)d_in[23];  const float* tf2b = (const float*)d_in[24];
    const float* tng  = (const float*)d_in[25];  const float* tnb  = (const float*)d_in[26];

    float *q, *k, *v, *t, *t2, *x, *y, *xn, *s, *h, *Afb;
    cudaGetSymbolAddress((void**)&q,  g_q);
    cudaGetSymbolAddress((void**)&k,  g_k);
    cudaGetSymbolAddress((void**)&v,  g_v);
    cudaGetSymbolAddress((void**)&t,  g_t);
    cudaGetSymbolAddress((void**)&t2, g_t2);
    cudaGetSymbolAddress((void**)&x,  g_x);
    cudaGetSymbolAddress((void**)&y,  g_y);
    cudaGetSymbolAddress((void**)&xn, g_xn);
    cudaGetSymbolAddress((void**)&s,  g_s);
    cudaGetSymbolAddress((void**)&h,  g_h);
    cudaGetSymbolAddress((void**)&Afb, g_A);

    float* out_ln = (float*)d_out;
    float* Ap = (out_size >= (BLD + BHLL)) ? ((float*)d_out + BLD) : Afb;

    const int M = BB * LL;       // 8192
    const long long LD = (long long)LL * DDIM;
    const long long LLs = (long long)LL * LL;

    // ---- outer multi-head attention ----
    sgemm(x0, aw_q, q, ab_q, nullptr, M, DDIM, DDIM, DDIM, DDIM, DDIM, 1.f, false, false, 1, 1, 0,0,0,0,0,0);
    sgemm(x0, aw_k, k, ab_k, nullptr, M, DDIM, DDIM, DDIM, DDIM, DDIM, 1.f, false, false, 1, 1, 0,0,0,0,0,0);
    sgemm(x0, aw_v, v, ab_v, nullptr, M, DDIM, DDIM, DDIM, DDIM, DDIM, 1.f, false, false, 1, 1, 0,0,0,0,0,0);

    // scores[b,h] = q_h @ k_h^T / 8  -> Ap  (batch = B*H, inner = H)
    sgemm(q, k, Ap, nullptr, nullptr, LL, LL, EE, DDIM, DDIM, LL, 0.125f, true, false,
          BB * HH, HH, LD, EE, LD, EE, (long long)HH * LLs, LLs);
    softmax_kernel<<<BB * HH * LL, 256>>>(Ap);

    // out = A @ v_h  -> t   (ldc=512, head offset 64)
    sgemm(Ap, v, t, nullptr, nullptr, LL, EE, LL, LL, DDIM, DDIM, 1.f, false, false,
          BB * HH, HH, (long long)HH * LLs, LLs, LD, EE, LD, EE);

    // t2 = t @ aw_o + ab_o + x0 ; x = LN(t2)
    sgemm(t, aw_o, t2, ab_o, x0, M, DDIM, DDIM, DDIM, DDIM, DDIM, 1.f, false, false, 1, 1, 0,0,0,0,0,0);
    ln_kernel<<<M, 128>>>(t2, nullptr, n1g, n1b, x);

    // y = x
    cudaMemcpyAsync(y, x, (size_t)BLD * sizeof(float), cudaMemcpyDeviceToDevice, 0);

    // ---- 3 temporal blocks ----
    for (int i = 0; i < NBLK; i++) {
        const float* Wq = tqw + (long long)i * DDIM * DDIM;  const float* bq = tqb + i * DDIM;
        const float* Wk = tkw + (long long)i * DDIM * DDIM;  const float* bk = tkb + i * DDIM;
        const float* Wv = tvw + (long long)i * DDIM * DDIM;  const float* bv = tvb + i * DDIM;
        const float* Wo = tow + (long long)i * DDIM * DDIM;  const float* bo = tob + i * DDIM;
        const float* W1 = tf1w + (long long)i * DDIM * DFF;  const float* b1 = tf1b + i * DFF;
        const float* W2 = tf2w + (long long)i * DFF * DDIM;  const float* b2 = tf2b + i * DDIM;
        const float* ng = tng + i * DDIM;                    const float* nb = tnb + i * DDIM;

        sgemm(y, Wq, q, bq, nullptr, M, DDIM, DDIM, DDIM, DDIM, DDIM, 1.f, false, false, 1, 1, 0,0,0,0,0,0);
        sgemm(y, Wk, k, bk, nullptr, M, DDIM, DDIM, DDIM, DDIM, DDIM, 1.f, false, false, 1, 1, 0,0,0,0,0,0);
        sgemm(y, Wv, v, bv, nullptr, M, DDIM, DDIM, DDIM, DDIM, DDIM, 1.f, false, false, 1, 1, 0,0,0,0,0,0);

        // scores[b] = q @ k^T (no scaling), batch = B
        sgemm(q, k, s, nullptr, nullptr, LL, LL, DDIM, DDIM, DDIM, LL, 1.f, true, false,
              BB, 1, LD, 0, LD, 0, LLs, 0);
        softmax_kernel<<<BB * LL, 256>>>(s);

        // out = probs @ v, batch = B
        sgemm(s, v, t, nullptr, nullptr, LL, DDIM, LL, LL, DDIM, DDIM, 1.f, false, false,
              BB, 1, LLs, 0, LD, 0, LD, 0);

        // transpose-reshape reinterpret
        permute_kernel<<<(BLD + 255) / 256, 256>>>(t, t2);

        // y = y + t2 @ Wo + bo
        sgemm(t2, Wo, y, bo, y, M, DDIM, DDIM, DDIM, DDIM, DDIM, 1.f, false, false, 1, 1, 0,0,0,0,0,0);

        // xn = LN(y); h = relu(xn@W1+b1); y = y + h@W2+b2
        ln_kernel<<<M, 128>>>(y, nullptr, ng, nb, xn);
        sgemm(xn, W1, h, b1, nullptr, M, DFF, DDIM, DDIM, DFF, DFF, 1.f, false, true, 1, 1, 0,0,0,0,0,0);
        sgemm(h,  W2, y, b2, y,       M, DDIM, DFF,  DFF,  DDIM, DDIM, 1.f, false, false, 1, 1, 0,0,0,0,0,0);
    }

    // ---- final: out = LN(x + y) ----
    ln_kernel<<<M, 128>>>(x, y, n2g, n2b, out_ln);
}

// round 3
// speedup vs baseline: 2.5671x; 1.0006x over previous
#include <cuda_runtime.h>
#include <cuda_bf16.h>

// ---------------- problem dims ----------------
#define BB   8
#define LL   1024
#define DDIM 512
#define HH   8
#define EE   64
#define DFF  2048
#define NBLK 3

#define BLD  (BB*LL*DDIM)        // 4194304
#define BLL  (BB*LL*LL)          // 8388608
#define BHLL (BB*HH*LL*LL)       // 67108864
#define BLDF (BB*LL*DFF)         // 16777216

// ---------------- scratch (device globals; no allocs allowed) ----------------
__device__ float g_q[BLD];
__device__ float g_k[BLD];
__device__ float g_v[BLD];
__device__ float g_t[BLD];
__device__ float g_t2[BLD];
__device__ float g_x[BLD];
__device__ float g_y[BLD];
__device__ float g_xn[BLD];
__device__ float g_s[BLL];
__device__ float g_h[BLDF];
__device__ float g_A[BHLL];     // fallback if d_out has no room for A

// ================= SGEMM v2: C = alpha * A@op(B) [+bias] [+res] [relu] =================
// BMxBN tile, BK=16, 256 threads, TMxTN per thread, float4 LDS/LDG/STG.
// As/Bs stored K-major with +4 padding (16B-aligned rows, low STS conflicts).
template<int BM, int BN, int TM, int TN, bool TB, bool RELU>
__global__ void __launch_bounds__(256) gemm_kernel(
    const float* __restrict__ A, const float* __restrict__ B,
    float* __restrict__ C,
    const float* __restrict__ bias,
    const float* __restrict__ res,
    int K, int lda, int ldb, int ldc,
    float alpha, int inner,
    long long sAo, long long sAi,
    long long sBo, long long sBi,
    long long sCo, long long sCi)
{
    int z  = blockIdx.z;
    int zo = z / inner;
    int zi = z - zo * inner;
    A += zo * sAo + zi * sAi;
    B += zo * sBo + zi * sBi;
    long long coff = zo * sCo + zi * sCi;
    C += coff;
    if (res) res += coff;

    __shared__ float As[16][BM + 4];
    __shared__ float Bs[16][BN + 4];

    const int tid  = threadIdx.x;
    const int NT   = BN / TN;              // threads along N
    const int tx   = tid % NT;
    const int ty   = tid / NT;
    const int row0 = blockIdx.y * BM;
    const int col0 = blockIdx.x * BN;

    float acc[TM][TN];
    #pragma unroll
    for (int i = 0; i < TM; i++)
        #pragma unroll
        for (int j = 0; j < TN; j++) acc[i][j] = 0.f;

    for (int k0 = 0; k0 < K; k0 += 16) {
        // ---- load A tile (BM x 16), transpose into As[k][m] ----
        #pragma unroll
        for (int i = 0; i < (BM * 16) / (256 * 4); i++) {
            int f  = tid + i * 256;        // float4 index
            int m  = f >> 2;
            int kq = f & 3;
            float4 vv = *(const float4*)&A[(size_t)(row0 + m) * lda + k0 + kq * 4];
            As[kq * 4 + 0][m] = vv.x;
            As[kq * 4 + 1][m] = vv.y;
            As[kq * 4 + 2][m] = vv.z;
            As[kq * 4 + 3][m] = vv.w;
        }
        // ---- load B tile ----
        if (TB) {
            // B is [N,K]: load float4 along K, transpose into Bs[k][n]
            #pragma unroll
            for (int i = 0; i < (BN * 16) / (256 * 4); i++) {
                int f  = tid + i * 256;
                int n  = f >> 2;
                int kq = f & 3;
                float4 vv = *(const float4*)&B[(size_t)(col0 + n) * ldb + k0 + kq * 4];
                Bs[kq * 4 + 0][n] = vv.x;
                Bs[kq * 4 + 1][n] = vv.y;
                Bs[kq * 4 + 2][n] = vv.z;
                Bs[kq * 4 + 3][n] = vv.w;
            }
        } else {
            // B is [K,N]: load float4 along N, store rows directly
            #pragma unroll
            for (int i = 0; i < (BN * 16) / (256 * 4); i++) {
                int f  = tid + i * 256;
                int k  = f / (BN / 4);
                int nq = f % (BN / 4);
                float4 vv = *(const float4*)&B[(size_t)(k0 + k) * ldb + col0 + nq * 4];
                *(float4*)&Bs[k][nq * 4] = vv;
            }
        }
        __syncthreads();

        // ---- compute ----
        #pragma unroll
        for (int kk = 0; kk < 16; kk++) {
            float a[TM], b[TN];
            #pragma unroll
            for (int i = 0; i < TM / 4; i++)
                *(float4*)&a[i * 4] = *(const float4*)&As[kk][ty * TM + i * 4];
            #pragma unroll
            for (int j = 0; j < TN / 4; j++)
                *(float4*)&b[j * 4] = *(const float4*)&Bs[kk][tx * TN + j * 4];
            #pragma unroll
            for (int i = 0; i < TM; i++)
                #pragma unroll
                for (int j = 0; j < TN; j++)
                    acc[i][j] += a[i] * b[j];
        }
        __syncthreads();
    }

    // ---- epilogue: float4 stores ----
    #pragma unroll
    for (int i = 0; i < TM; i++) {
        int m = row0 + ty * TM + i;
        #pragma unroll
        for (int j4 = 0; j4 < TN / 4; j4++) {
            int n = col0 + tx * TN + j4 * 4;
            float4 vv;
            vv.x = acc[i][j4 * 4 + 0] * alpha;
            vv.y = acc[i][j4 * 4 + 1] * alpha;
            vv.z = acc[i][j4 * 4 + 2] * alpha;
            vv.w = acc[i][j4 * 4 + 3] * alpha;
            if (bias) {
                float4 bb = *(const float4*)&bias[n];
                vv.x += bb.x; vv.y += bb.y; vv.z += bb.z; vv.w += bb.w;
            }
            if (res) {
                float4 rr = *(const float4*)&res[(size_t)m * ldc + n];
                vv.x += rr.x; vv.y += rr.y; vv.z += rr.z; vv.w += rr.w;
            }
            if (RELU) {
                vv.x = fmaxf(vv.x, 0.f); vv.y = fmaxf(vv.y, 0.f);
                vv.z = fmaxf(vv.z, 0.f); vv.w = fmaxf(vv.w, 0.f);
            }
            *(float4*)&C[(size_t)m * ldc + n] = vv;
        }
    }
}

// ---------------- row softmax, row length 1024, 256 threads ----------------
__global__ void softmax_kernel(float* __restrict__ P)
{
    long long base = (long long)blockIdx.x * 1024;
    int tid = threadIdx.x;
    __shared__ float red[256];

    float4 vv = *(const float4*)&P[base + tid * 4];
    float v[4] = {vv.x, vv.y, vv.z, vv.w};
    float mx = fmaxf(fmaxf(v[0], v[1]), fmaxf(v[2], v[3]));
    red[tid] = mx; __syncthreads();
    for (int s = 128; s > 0; s >>= 1) {
        if (tid < s) red[tid] = fmaxf(red[tid], red[tid + s]);
        __syncthreads();
    }
    mx = red[0]; __syncthreads();

    float sum = 0.f;
    #pragma unroll
    for (int i = 0; i < 4; i++) { v[i] = __expf(v[i] - mx); sum += v[i]; }
    red[tid] = sum; __syncthreads();
    for (int s = 128; s > 0; s >>= 1) {
        if (tid < s) red[tid] += red[tid + s];
        __syncthreads();
    }
    float inv = 1.f / red[0];
    vv.x = v[0] * inv; vv.y = v[1] * inv; vv.z = v[2] * inv; vv.w = v[3] * inv;
    *(float4*)&P[base + tid * 4] = vv;
}

// ---------------- layernorm over D=512; input = a (+ b if b!=null) ----------------
__global__ void ln_kernel(const float* __restrict__ a, const float* __restrict__ b,
                          const float* __restrict__ g, const float* __restrict__ beta,
                          float* __restrict__ out)
{
    long long base = (long long)blockIdx.x * 512;
    int tid = threadIdx.x;   // 128 threads, 4 floats each
    __shared__ float red[128];

    float4 xv = *(const float4*)&a[base + tid * 4];
    if (b) {
        float4 bv = *(const float4*)&b[base + tid * 4];
        xv.x += bv.x; xv.y += bv.y; xv.z += bv.z; xv.w += bv.w;
    }

    red[tid] = xv.x + xv.y + xv.z + xv.w; __syncthreads();
    for (int s = 64; s > 0; s >>= 1) {
        if (tid < s) red[tid] += red[tid + s];
        __syncthreads();
    }
    float mean = red[0] * (1.f / 512.f);
    __syncthreads();

    float d0 = xv.x - mean, d1 = xv.y - mean, d2 = xv.z - mean, d3 = xv.w - mean;
    red[tid] = d0 * d0 + d1 * d1 + d2 * d2 + d3 * d3; __syncthreads();
    for (int s = 64; s > 0; s >>= 1) {
        if (tid < s) red[tid] += red[tid + s];
        __syncthreads();
    }
    float rstd = rsqrtf(red[0] * (1.f / 512.f) + 1e-5f);

    float4 gv = *(const float4*)&g[tid * 4];
    float4 bt = *(const float4*)&beta[tid * 4];
    float4 ov;
    ov.x = d0 * rstd * gv.x + bt.x;
    ov.y = d1 * rstd * gv.y + bt.y;
    ov.z = d2 * rstd * gv.z + bt.z;
    ov.w = d3 * rstd * gv.w + bt.w;
    *(float4*)&out[base + tid * 4] = ov;
}

// ---------------- temporal "transpose-reshape": out[b, f] = in[b, (f%L)*D + f/L] ----------------
__global__ void permute_kernel(const float* __restrict__ in, float* __restrict__ out)
{
    long long i = (long long)blockIdx.x * 256 + threadIdx.x;
    if (i >= (long long)BLD) return;
    long long bidx = i / (LL * DDIM);
    int f = (int)(i - bidx * (LL * DDIM));
    out[i] = in[bidx * (LL * DDIM) + (long long)(f & (LL - 1)) * DDIM + (f >> 10)];
}

// ---------------- host-side dispatch ----------------
static void sgemm(const float* A, const float* B, float* C,
                  const float* bias, const float* res,
                  int M, int N, int K, int lda, int ldb, int ldc,
                  float alpha, bool tb, bool relu,
                  int batch, int inner,
                  long long sAo, long long sAi,
                  long long sBo, long long sBi,
                  long long sCo, long long sCi)
{
    if (N % 128 == 0) {
        dim3 grid(N / 128, M / 128, batch);
        if (tb) {
            if (relu) gemm_kernel<128,128,8,8,true ,true ><<<grid,256>>>(A,B,C,bias,res,K,lda,ldb,ldc,alpha,inner,sAo,sAi,sBo,sBi,sCo,sCi);
            else      gemm_kernel<128,128,8,8,true ,false><<<grid,256>>>(A,B,C,bias,res,K,lda,ldb,ldc,alpha,inner,sAo,sAi,sBo,sBi,sCo,sCi);
        } else {
            if (relu) gemm_kernel<128,128,8,8,false,true ><<<grid,256>>>(A,B,C,bias,res,K,lda,ldb,ldc,alpha,inner,sAo,sAi,sBo,sBi,sCo,sCi);
            else      gemm_kernel<128,128,8,8,false,false><<<grid,256>>>(A,B,C,bias,res,K,lda,ldb,ldc,alpha,inner,sAo,sAi,sBo,sBi,sCo,sCi);
        }
    } else {
        // N multiple of 64 (the head-sliced A@V GEMM)
        dim3 grid(N / 64, M / 128, batch);
        if (tb) {
            if (relu) gemm_kernel<128,64,8,4,true ,true ><<<grid,256>>>(A,B,C,bias,res,K,lda,ldb,ldc,alpha,inner,sAo,sAi,sBo,sBi,sCo,sCi);
            else      gemm_kernel<128,64,8,4,true ,false><<<grid,256>>>(A,B,C,bias,res,K,lda,ldb,ldc,alpha,inner,sAo,sAi,sBo,sBi,sCo,sCi);
        } else {
            if (relu) gemm_kernel<128,64,8,4,false,true ><<<grid,256>>>(A,B,C,bias,res,K,lda,ldb,ldc,alpha,inner,sAo,sAi,sBo,sBi,sCo,sCi);
            else      gemm_kernel<128,64,8,4,false,false><<<grid,256>>>(A,B,C,bias,res,K,lda,ldb,ldc,alpha,inner,sAo,sAi,sBo,sBi,sCo,sCi);
        }
    }
}

extern "C" void kernel_launch(void* const* d_in, const int* in_sizes, int n_in,
                              void* d_out, int out_size)
{
    const float* x0   = (const float*)d_in[0];
    const float* aw_q = (const float*)d_in[1];   const float* ab_q = (const float*)d_in[2];
    const float* aw_k = (const float*)d_in[3];   const float* ab_k = (const float*)d_in[4];
    const float* aw_v = (const float*)d_in[5];   const float* ab_v = (const float*)d_in[6];
    const float* aw_o = (const float*)d_in[7];   const float* ab_o = (const float*)d_in[8];
    const float* n1g  = (const float*)d_in[9];   const float* n1b  = (const float*)d_in[10];
    const float* n2g  = (const float*)d_in[11];  const float* n2b  = (const float*)d_in[12];
    const float* tqw  = (const float*)d_in[13];  const float* tqb  = (const float*)d_in[14];
    const float* tkw  = (const float*)d_in[15];  const float* tkb  = (const float*)d_in[16];
    const float* tvw  = (const float*)d_in[17];  const float* tvb  = (const float*)d_in[18];
    const float* tow  = (const float*)d_in[19];  const float* tob  = (const float*)d_in[20];
    const float* tf1w = (const float*)d_in[21];  const float* tf1b = (const float*)d_in[22];
    const float* tf2w = (const float*)d_in[23];  const float* tf2b = (const float*)d_in[24];
    const float* tng  = (const float*)d_in[25];  const float* tnb  = (const float*)d_in[26];

    float *q, *k, *v, *t, *t2, *x, *y, *xn, *s, *h, *Afb;
    cudaGetSymbolAddress((void**)&q,  g_q);
    cudaGetSymbolAddress((void**)&k,  g_k);
    cudaGetSymbolAddress((void**)&v,  g_v);
    cudaGetSymbolAddress((void**)&t,  g_t);
    cudaGetSymbolAddress((void**)&t2, g_t2);
    cudaGetSymbolAddress((void**)&x,  g_x);
    cudaGetSymbolAddress((void**)&y,  g_y);
    cudaGetSymbolAddress((void**)&xn, g_xn);
    cudaGetSymbolAddress((void**)&s,  g_s);
    cudaGetSymbolAddress((void**)&h,  g_h);
    cudaGetSymbolAddress((void**)&Afb, g_A);

    float* out_ln = (float*)d_out;
    float* Ap = (out_size >= (BLD + BHLL)) ? ((float*)d_out + BLD) : Afb;

    const int M = BB * LL;       // 8192
    const long long LD = (long long)LL * DDIM;
    const long long LLs = (long long)LL * LL;

    // ---- outer multi-head attention ----
    sgemm(x0, aw_q, q, ab_q, nullptr, M, DDIM, DDIM, DDIM, DDIM, DDIM, 1.f, false, false, 1, 1, 0,0,0,0,0,0);
    sgemm(x0, aw_k, k, ab_k, nullptr, M, DDIM, DDIM, DDIM, DDIM, DDIM, 1.f, false, false, 1, 1, 0,0,0,0,0,0);
    sgemm(x0, aw_v, v, ab_v, nullptr, M, DDIM, DDIM, DDIM, DDIM, DDIM, 1.f, false, false, 1, 1, 0,0,0,0,0,0);

    // scores[b,h] = q_h @ k_h^T / 8  -> Ap  (batch = B*H, inner = H)
    sgemm(q, k, Ap, nullptr, nullptr, LL, LL, EE, DDIM, DDIM, LL, 0.125f, true, false,
          BB * HH, HH, LD, EE, LD, EE, (long long)HH * LLs, LLs);
    softmax_kernel<<<BB * HH * LL, 256>>>(Ap);

    // out = A @ v_h  -> t   (ldc=512, head offset 64)
    sgemm(Ap, v, t, nullptr, nullptr, LL, EE, LL, LL, DDIM, DDIM, 1.f, false, false,
          BB * HH, HH, (long long)HH * LLs, LLs, LD, EE, LD, EE);

    // t2 = t @ aw_o + ab_o + x0 ; x = LN(t2)
    sgemm(t, aw_o, t2, ab_o, x0, M, DDIM, DDIM, DDIM, DDIM, DDIM, 1.f, false, false, 1, 1, 0,0,0,0,0,0);
    ln_kernel<<<M, 128>>>(t2, nullptr, n1g, n1b, x);

    // y = x
    cudaMemcpyAsync(y, x, (size_t)BLD * sizeof(float), cudaMemcpyDeviceToDevice, 0);

    // ---- 3 temporal blocks ----
    for (int i = 0; i < NBLK; i++) {
        const float* Wq = tqw + (long long)i * DDIM * DDIM;  const float* bq = tqb + i * DDIM;
        const float* Wk = tkw + (long long)i * DDIM * DDIM;  const float* bk = tkb + i * DDIM;
        const float* Wv = tvw + (long long)i * DDIM * DDIM;  const float* bv = tvb + i * DDIM;
        const float* Wo = tow + (long long)i * DDIM * DDIM;  const float* bo = tob + i * DDIM;
        const float* W1 = tf1w + (long long)i * DDIM * DFF;  const float* b1 = tf1b + i * DFF;
        const float* W2 = tf2w + (long long)i * DFF * DDIM;  const float* b2 = tf2b + i * DDIM;
        const float* ng = tng + i * DDIM;                    const float* nb = tnb + i * DDIM;

        sgemm(y, Wq, q, bq, nullptr, M, DDIM, DDIM, DDIM, DDIM, DDIM, 1.f, false, false, 1, 1, 0,0,0,0,0,0);
        sgemm(y, Wk, k, bk, nullptr, M, DDIM, DDIM, DDIM, DDIM, DDIM, 1.f, false, false, 1, 1, 0,0,0,0,0,0);
        sgemm(y, Wv, v, bv, nullptr, M, DDIM, DDIM, DDIM, DDIM, DDIM, 1.f, false, false, 1, 1, 0,0,0,0,0,0);

        // scores[b] = q @ k^T (no scaling), batch = B
        sgemm(q, k, s, nullptr, nullptr, LL, LL, DDIM, DDIM, DDIM, LL, 1.f, true, false,
              BB, 1, LD, 0, LD, 0, LLs, 0);
        softmax_kernel<<<BB * LL, 256>>>(s);

        // out = probs @ v, batch = B
        sgemm(s, v, t, nullptr, nullptr, LL, DDIM, LL, LL, DDIM, DDIM, 1.f, false, false,
              BB, 1, LLs, 0, LD, 0, LD, 0);

        // transpose-reshape reinterpret
        permute_kernel<<<(BLD + 255) / 256, 256>>>(t, t2);

        // y = y + t2 @ Wo + bo
        sgemm(t2, Wo, y, bo, y, M, DDIM, DDIM, DDIM, DDIM, DDIM, 1.f, false, false, 1, 1, 0,0,0,0,0,0);

        // xn = LN(y); h = relu(xn@W1+b1); y = y + h@W2+b2
        ln_kernel<<<M, 128>>>(y, nullptr, ng, nb, xn);
        sgemm(xn, W1, h, b1, nullptr, M, DFF, DDIM, DDIM, DFF, DFF, 1.f, false, true, 1, 1, 0,0,0,0,0,0);
        sgemm(h,  W2, y, b2, y,       M, DDIM, DFF,  DFF,  DDIM, DDIM, 1.f, false, false, 1, 1, 0,0,0,0,0,0);
    }

    // ---- final: out = LN(x + y) ----
    ln_kernel<<<M, 128>>>(x, y, n2g, n2b, out_ln);
}

// round 5
// speedup vs baseline: 5.5038x; 2.1440x over previous
#include <cuda_runtime.h>
#include <cuda_fp16.h>
#include <cstdint>

#define BB   8
#define LL   1024
#define DDIM 512
#define HH   8
#define EE   64
#define DFF  2048
#define NBLK 3
#define BLD  (BB*LL*DDIM)
#define BLL  (BB*LL*LL)
#define BHLL (BB*HH*LL*LL)
#define BLDF (BB*LL*DFF)
#define DD2  (DDIM*DDIM)

// ---------------- scratch ----------------
__device__ float g_q[BLD];
__device__ float g_k[BLD];
__device__ float g_v[BLD];
__device__ float g_vt[BLD];
__device__ float g_t[BLD];
__device__ float g_t2[BLD];
__device__ float g_x[BLD];
__device__ float g_y[BLD];
__device__ float g_xn[BLD];
__device__ float g_s[BLL];
__device__ float g_h[BLDF];
__device__ float g_A[BHLL];
__device__ float g_awt[4*DD2];
__device__ float g_twt[4*NBLK*DD2];
__device__ float g_f1t[NBLK*DDIM*DFF];
__device__ float g_f2t[NBLK*DFF*DDIM];

// ---------------- helpers ----------------
__device__ __forceinline__ void mma16816(float* d, const uint32_t* a, uint32_t b0, uint32_t b1) {
    asm volatile(
        "mma.sync.aligned.m16n8k16.row.col.f32.f16.f16.f32 "
        "{%0,%1,%2,%3}, {%4,%5,%6,%7}, {%8,%9}, {%0,%1,%2,%3};"
        : "+f"(d[0]), "+f"(d[1]), "+f"(d[2]), "+f"(d[3])
        : "r"(a[0]), "r"(a[1]), "r"(a[2]), "r"(a[3]), "r"(b0), "r"(b1));
}
__device__ __forceinline__ void split4(float4 v, uint2& hi, uint2& lo) {
    __half2 h01 = __floats2half2_rn(v.x, v.y);
    __half2 h23 = __floats2half2_rn(v.z, v.w);
    float2 f01 = __half22float2(h01);
    float2 f23 = __half22float2(h23);
    __half2 l01 = __floats2half2_rn(v.x - f01.x, v.y - f01.y);
    __half2 l23 = __floats2half2_rn(v.z - f23.x, v.w - f23.y);
    hi.x = *(uint32_t*)&h01; hi.y = *(uint32_t*)&h23;
    lo.x = *(uint32_t*)&l01; lo.y = *(uint32_t*)&l23;
}

// ============ fp16 hi/lo split tensor GEMM ============
// C[M,N] = alpha*A[M,K]@B[N,K]^T (+bias)(+res)(relu); fp32-grade via h*h+h*l+l*h.
// CTA 128x128 (or 128x64), BK=32, 512 threads = 16 warps (4x4), warp tile 32x(BN/4).
template<int BN, bool RELU>
__global__ void __launch_bounds__(512) hgemm(
    const float* __restrict__ A, const float* __restrict__ B, float* __restrict__ C,
    const float* __restrict__ bias, const float* __restrict__ res,
    int K, int lda, int ldb, int ldc, float alpha, int inner,
    long long sAo, long long sAi, long long sBo, long long sBi,
    long long sCo, long long sCi)
{
    constexpr int LDS_ = 40;                    // BK=32 halves + 8 pad
    constexpr int ABYT = 128 * LDS_;            // halves
    constexpr int BBYT = BN * LDS_;
    constexpr int STAGE = 2 * ABYT + 2 * BBYT;  // Ah,Al,Bh,Bl
    constexpr int NA   = BN / 32;               // n-atoms per warp (warp n-tile = BN/4)
    constexpr int NA4  = 2;                     // A float4 loads per thread
    constexpr int NB4  = BN / 64;               // B float4 loads per thread

    extern __shared__ __half smb[];

    int z  = blockIdx.z;
    int zo = z / inner;
    int zi = z - zo * inner;
    A += zo * sAo + zi * sAi;
    B += zo * sBo + zi * sBi;
    long long coff = zo * sCo + zi * sCi;
    C += coff;
    if (res) res += coff;

    const int tid  = threadIdx.x;
    const int wid  = tid >> 5, lane = tid & 31;
    const int g    = lane >> 2, t4 = lane & 3;
    const int row0 = blockIdx.y * 128, col0 = blockIdx.x * BN;
    const int arow = (wid & 3) * 32;
    const int brow = (wid >> 2) * (BN / 4);

    float acc[2][NA][4];
    #pragma unroll
    for (int i = 0; i < 2; i++)
        #pragma unroll
        for (int j = 0; j < NA; j++)
            #pragma unroll
            for (int e = 0; e < 4; e++) acc[i][j][e] = 0.f;

    float4 av[NA4], bv[NB4];

    auto load_chunk = [&](int c) {
        const int k0 = c * 32;
        #pragma unroll
        for (int i = 0; i < NA4; i++) {
            int f = tid + i * 512; int r = f >> 3, kq = f & 7;
            av[i] = *(const float4*)(A + (size_t)(row0 + r) * lda + k0 + kq * 4);
        }
        #pragma unroll
        for (int i = 0; i < NB4; i++) {
            int f = tid + i * 512; int r = f >> 3, kq = f & 7;
            bv[i] = *(const float4*)(B + (size_t)(col0 + r) * ldb + k0 + kq * 4);
        }
    };
    auto store_chunk = [&](int buf) {
        __half* pAh = smb + buf * STAGE;
        __half* pAl = pAh + ABYT;
        __half* pBh = pAl + ABYT;
        __half* pBl = pBh + BBYT;
        #pragma unroll
        for (int i = 0; i < NA4; i++) {
            int f = tid + i * 512; int r = f >> 3, kq = f & 7;
            uint2 h, l; split4(av[i], h, l);
            *(uint2*)&pAh[r * LDS_ + kq * 4] = h;
            *(uint2*)&pAl[r * LDS_ + kq * 4] = l;
        }
        #pragma unroll
        for (int i = 0; i < NB4; i++) {
            int f = tid + i * 512; int r = f >> 3, kq = f & 7;
            uint2 h, l; split4(bv[i], h, l);
            *(uint2*)&pBh[r * LDS_ + kq * 4] = h;
            *(uint2*)&pBl[r * LDS_ + kq * 4] = l;
        }
    };

    const int NC = K >> 5;
    load_chunk(0);
    store_chunk(0);
    __syncthreads();

    for (int c = 0; c < NC; c++) {
        const int buf = c & 1;
        if (c + 1 < NC) load_chunk(c + 1);

        const __half* pAh = smb + buf * STAGE;
        const __half* pAl = pAh + ABYT;
        const __half* pBh = pAl + ABYT;
        const __half* pBl = pBh + BBYT;

        #pragma unroll
        for (int ka = 0; ka < 2; ka++) {
            const int cb = ka * 16 + t4 * 2;
            uint32_t ah[2][4], al[2][4];
            #pragma unroll
            for (int ma = 0; ma < 2; ma++) {
                int r0 = arow + ma * 16 + g;
                ah[ma][0] = *(const uint32_t*)&pAh[r0 * LDS_ + cb];
                ah[ma][1] = *(const uint32_t*)&pAh[(r0 + 8) * LDS_ + cb];
                ah[ma][2] = *(const uint32_t*)&pAh[r0 * LDS_ + cb + 8];
                ah[ma][3] = *(const uint32_t*)&pAh[(r0 + 8) * LDS_ + cb + 8];
                al[ma][0] = *(const uint32_t*)&pAl[r0 * LDS_ + cb];
                al[ma][1] = *(const uint32_t*)&pAl[(r0 + 8) * LDS_ + cb];
                al[ma][2] = *(const uint32_t*)&pAl[r0 * LDS_ + cb + 8];
                al[ma][3] = *(const uint32_t*)&pAl[(r0 + 8) * LDS_ + cb + 8];
            }
            #pragma unroll
            for (int na = 0; na < NA; na++) {
                int rb = (brow + na * 8 + g) * LDS_ + cb;
                uint32_t bh0 = *(const uint32_t*)&pBh[rb];
                uint32_t bh1 = *(const uint32_t*)&pBh[rb + 8];
                uint32_t bl0 = *(const uint32_t*)&pBl[rb];
                uint32_t bl1 = *(const uint32_t*)&pBl[rb + 8];
                #pragma unroll
                for (int ma = 0; ma < 2; ma++) {
                    mma16816(acc[ma][na], ah[ma], bh0, bh1);
                    mma16816(acc[ma][na], ah[ma], bl0, bl1);
                    mma16816(acc[ma][na], al[ma], bh0, bh1);
                }
            }
        }
        if (c + 1 < NC) store_chunk(buf ^ 1);
        __syncthreads();
    }

    // ---- epilogue ----
    #pragma unroll
    for (int ma = 0; ma < 2; ma++) {
        #pragma unroll
        for (int na = 0; na < NA; na++) {
            int r_ = row0 + arow + ma * 16 + g;
            int n_ = col0 + brow + na * 8 + t4 * 2;
            float2 bb = bias ? *(const float2*)&bias[n_] : make_float2(0.f, 0.f);
            #pragma unroll
            for (int half_ = 0; half_ < 2; half_++) {
                int m = r_ + half_ * 8;
                float2 v;
                v.x = acc[ma][na][half_ * 2 + 0] * alpha + bb.x;
                v.y = acc[ma][na][half_ * 2 + 1] * alpha + bb.y;
                if (res) {
                    float2 rr = *(const float2*)&res[(size_t)m * ldc + n_];
                    v.x += rr.x; v.y += rr.y;
                }
                if (RELU) { v.x = fmaxf(v.x, 0.f); v.y = fmaxf(v.y, 0.f); }
                *(float2*)&C[(size_t)m * ldc + n_] = v;
            }
        }
    }
}

// ---------------- tiled transpose: out[C,R] = in[R,C]^T, batched ----------------
__global__ void transpose_kernel(const float* __restrict__ in, float* __restrict__ out, int R, int C)
{
    __shared__ float tile[32][33];
    size_t bo = (size_t)blockIdx.z * R * C;
    int c0 = blockIdx.x * 32, r0 = blockIdx.y * 32;
    int tx = threadIdx.x, ty = threadIdx.y;
    #pragma unroll
    for (int j = 0; j < 4; j++)
        tile[ty + j * 8][tx] = in[bo + (size_t)(r0 + ty + j * 8) * C + c0 + tx];
    __syncthreads();
    #pragma unroll
    for (int j = 0; j < 4; j++)
        out[bo + (size_t)(c0 + ty + j * 8) * R + r0 + tx] = tile[tx][ty + j * 8];
}

// ---------------- softmax (rows of 1024) ----------------
__global__ void softmax_kernel(float* __restrict__ P)
{
    long long base = (long long)blockIdx.x * 1024;
    int tid = threadIdx.x;
    __shared__ float red[256];
    float4 vv = *(const float4*)&P[base + tid * 4];
    float v[4] = {vv.x, vv.y, vv.z, vv.w};
    float mx = fmaxf(fmaxf(v[0], v[1]), fmaxf(v[2], v[3]));
    red[tid] = mx; __syncthreads();
    for (int s = 128; s > 0; s >>= 1) { if (tid < s) red[tid] = fmaxf(red[tid], red[tid + s]); __syncthreads(); }
    mx = red[0]; __syncthreads();
    float sum = 0.f;
    #pragma unroll
    for (int i = 0; i < 4; i++) { v[i] = __expf(v[i] - mx); sum += v[i]; }
    red[tid] = sum; __syncthreads();
    for (int s = 128; s > 0; s >>= 1) { if (tid < s) red[tid] += red[tid + s]; __syncthreads(); }
    float inv = 1.f / red[0];
    vv.x = v[0] * inv; vv.y = v[1] * inv; vv.z = v[2] * inv; vv.w = v[3] * inv;
    *(float4*)&P[base + tid * 4] = vv;
}

// ---------------- layernorm over D=512 ----------------
__global__ void ln_kernel(const float* __restrict__ a, const float* __restrict__ b,
                          const float* __restrict__ g, const float* __restrict__ beta,
                          float* __restrict__ out)
{
    long long base = (long long)blockIdx.x * 512;
    int tid = threadIdx.x;   // 128
    __shared__ float red[128];
    float4 xv = *(const float4*)&a[base + tid * 4];
    if (b) {
        float4 bv = *(const float4*)&b[base + tid * 4];
        xv.x += bv.x; xv.y += bv.y; xv.z += bv.z; xv.w += bv.w;
    }
    red[tid] = xv.x + xv.y + xv.z + xv.w; __syncthreads();
    for (int s = 64; s > 0; s >>= 1) { if (tid < s) red[tid] += red[tid + s]; __syncthreads(); }
    float mean = red[0] * (1.f / 512.f);
    __syncthreads();
    float d0 = xv.x - mean, d1 = xv.y - mean, d2 = xv.z - mean, d3 = xv.w - mean;
    red[tid] = d0 * d0 + d1 * d1 + d2 * d2 + d3 * d3; __syncthreads();
    for (int s = 64; s > 0; s >>= 1) { if (tid < s) red[tid] += red[tid + s]; __syncthreads(); }
    float rstd = rsqrtf(red[0] * (1.f / 512.f) + 1e-5f);
    float4 gv = *(const float4*)&g[tid * 4];
    float4 bt = *(const float4*)&beta[tid * 4];
    float4 ov;
    ov.x = d0 * rstd * gv.x + bt.x;
    ov.y = d1 * rstd * gv.y + bt.y;
    ov.z = d2 * rstd * gv.z + bt.z;
    ov.w = d3 * rstd * gv.w + bt.w;
    *(float4*)&out[base + tid * 4] = ov;
}

// ---------------- temporal "transpose-reshape" ----------------
__global__ void permute_kernel(const float* __restrict__ in, float* __restrict__ out)
{
    long long i = (long long)blockIdx.x * 256 + threadIdx.x;
    if (i >= (long long)BLD) return;
    long long b = i / (LL * DDIM);
    int f = (int)(i - b * (LL * DDIM));
    out[i] = in[b * (LL * DDIM) + (long long)(f & (LL - 1)) * DDIM + (f >> 10)];
}

// ---------------- host dispatch ----------------
static void tcg(const float* A, const float* B, float* C,
                const float* bias, const float* res,
                int M, int N, int K, int lda, int ldb, int ldc,
                float alpha, bool relu, int batch, int inner,
                long long sAo, long long sAi, long long sBo, long long sBi,
                long long sCo, long long sCi)
{
    if (N % 128 == 0) {
        dim3 g(N / 128, M / 128, batch);
        size_t sm = 2ull * (2 * 128 * 40 + 2 * 128 * 40) * sizeof(__half);  // 81920
        if (relu) {
            cudaFuncSetAttribute(hgemm<128, true >, cudaFuncAttributeMaxDynamicSharedMemorySize, (int)sm);
            hgemm<128, true ><<<g, 512, sm>>>(A, B, C, bias, res, K, lda, ldb, ldc, alpha, inner, sAo, sAi, sBo, sBi, sCo, sCi);
        } else {
            cudaFuncSetAttribute(hgemm<128, false>, cudaFuncAttributeMaxDynamicSharedMemorySize, (int)sm);
            hgemm<128, false><<<g, 512, sm>>>(A, B, C, bias, res, K, lda, ldb, ldc, alpha, inner, sAo, sAi, sBo, sBi, sCo, sCi);
        }
    } else { // N == 64
        dim3 g(N / 64, M / 128, batch);
        size_t sm = 2ull * (2 * 128 * 40 + 2 * 64 * 40) * sizeof(__half);   // 61440
        cudaFuncSetAttribute(hgemm<64, false>, cudaFuncAttributeMaxDynamicSharedMemorySize, (int)sm);
        hgemm<64, false><<<g, 512, sm>>>(A, B, C, bias, res, K, lda, ldb, ldc, alpha, inner, sAo, sAi, sBo, sBi, sCo, sCi);
    }
}

extern "C" void kernel_launch(void* const* d_in, const int* in_sizes, int n_in,
                              void* d_out, int out_size)
{
    const float* x0   = (const float*)d_in[0];
    const float* aw_q = (const float*)d_in[1];   const float* ab_q = (const float*)d_in[2];
    const float* aw_k = (const float*)d_in[3];   const float* ab_k = (const float*)d_in[4];
    const float* aw_v = (const float*)d_in[5];   const float* ab_v = (const float*)d_in[6];
    const float* aw_o = (const float*)d_in[7];   const float* ab_o = (const float*)d_in[8];
    const float* n1g  = (const float*)d_in[9];   const float* n1b  = (const float*)d_in[10];
    const float* n2g  = (const float*)d_in[11];  const float* n2b  = (const float*)d_in[12];
    const float* tqw  = (const float*)d_in[13];  const float* tqb  = (const float*)d_in[14];
    const float* tkw  = (const float*)d_in[15];  const float* tkb  = (const float*)d_in[16];
    const float* tvw  = (const float*)d_in[17];  const float* tvb  = (const float*)d_in[18];
    const float* tow  = (const float*)d_in[19];  const float* tob  = (const float*)d_in[20];
    const float* tf1w = (const float*)d_in[21];  const float* tf1b = (const float*)d_in[22];
    const float* tf2w = (const float*)d_in[23];  const float* tf2b = (const float*)d_in[24];
    const float* tng  = (const float*)d_in[25];  const float* tnb  = (const float*)d_in[26];

    float *q,*k,*v,*vt,*t,*t2,*x,*y,*xn,*s,*h,*Afb,*awt,*twt,*f1t,*f2t;
    cudaGetSymbolAddress((void**)&q,  g_q);
    cudaGetSymbolAddress((void**)&k,  g_k);
    cudaGetSymbolAddress((void**)&v,  g_v);
    cudaGetSymbolAddress((void**)&vt, g_vt);
    cudaGetSymbolAddress((void**)&t,  g_t);
    cudaGetSymbolAddress((void**)&t2, g_t2);
    cudaGetSymbolAddress((void**)&x,  g_x);
    cudaGetSymbolAddress((void**)&y,  g_y);
    cudaGetSymbolAddress((void**)&xn, g_xn);
    cudaGetSymbolAddress((void**)&s,  g_s);
    cudaGetSymbolAddress((void**)&h,  g_h);
    cudaGetSymbolAddress((void**)&Afb, g_A);
    cudaGetSymbolAddress((void**)&awt, g_awt);
    cudaGetSymbolAddress((void**)&twt, g_twt);
    cudaGetSymbolAddress((void**)&f1t, g_f1t);
    cudaGetSymbolAddress((void**)&f2t, g_f2t);

    float* out_ln = (float*)d_out;
    float* Ap = (out_size >= (BLD + BHLL)) ? ((float*)d_out + BLD) : Afb;

    const int M = BB * LL;
    const long long LD  = (long long)LL * DDIM;
    const long long LLs = (long long)LL * LL;
    dim3 tb(32, 8);

    // ---- transpose all weights to [N,K] ----
    transpose_kernel<<<dim3(16,16,1), tb>>>(aw_q, awt + 0*DD2, DDIM, DDIM);
    transpose_kernel<<<dim3(16,16,1), tb>>>(aw_k, awt + 1*DD2, DDIM, DDIM);
    transpose_kernel<<<dim3(16,16,1), tb>>>(aw_v, awt + 2*DD2, DDIM, DDIM);
    transpose_kernel<<<dim3(16,16,1), tb>>>(aw_o, awt + 3*DD2, DDIM, DDIM);
    transpose_kernel<<<dim3(16,16,NBLK), tb>>>(tqw, twt + 0*NBLK*DD2, DDIM, DDIM);
    transpose_kernel<<<dim3(16,16,NBLK), tb>>>(tkw, twt + 1*NBLK*DD2, DDIM, DDIM);
    transpose_kernel<<<dim3(16,16,NBLK), tb>>>(tvw, twt + 2*NBLK*DD2, DDIM, DDIM);
    transpose_kernel<<<dim3(16,16,NBLK), tb>>>(tow, twt + 3*NBLK*DD2, DDIM, DDIM);
    transpose_kernel<<<dim3(64,16,NBLK), tb>>>(tf1w, f1t, DDIM, DFF);
    transpose_kernel<<<dim3(16,64,NBLK), tb>>>(tf2w, f2t, DFF, DDIM);

    // ---- outer MHA ----
    tcg(x0, awt + 0*DD2, q, ab_q, nullptr, M, DDIM, DDIM, DDIM, DDIM, DDIM, 1.f, false, 1, 1, 0,0,0,0,0,0);
    tcg(x0, awt + 1*DD2, k, ab_k, nullptr, M, DDIM, DDIM, DDIM, DDIM, DDIM, 1.f, false, 1, 1, 0,0,0,0,0,0);
    tcg(x0, awt + 2*DD2, v, ab_v, nullptr, M, DDIM, DDIM, DDIM, DDIM, DDIM, 1.f, false, 1, 1, 0,0,0,0,0,0);
    transpose_kernel<<<dim3(16,32,BB), tb>>>(v, vt, LL, DDIM);   // vt[b] = v[b]^T  [D,L]

    // scores: q_h @ k_h^T / 8
    tcg(q, k, Ap, nullptr, nullptr, LL, LL, EE, DDIM, DDIM, LL, 0.125f, false,
        BB * HH, HH, LD, EE, LD, EE, (long long)HH * LLs, LLs);
    softmax_kernel<<<BB * HH * LL, 256>>>(Ap);

    // out = A @ v_h : B = vt head slice [64, L]
    tcg(Ap, vt, t, nullptr, nullptr, LL, EE, LL, LL, LL, DDIM, 1.f, false,
        BB * HH, HH, (long long)HH * LLs, LLs, LD, (long long)EE * LL, LD, EE);

    tcg(t, awt + 3*DD2, t2, ab_o, x0, M, DDIM, DDIM, DDIM, DDIM, DDIM, 1.f, false, 1, 1, 0,0,0,0,0,0);
    ln_kernel<<<M, 128>>>(t2, nullptr, n1g, n1b, x);
    cudaMemcpyAsync(y, x, (size_t)BLD * sizeof(float), cudaMemcpyDeviceToDevice, 0);

    // ---- temporal blocks ----
    for (int i = 0; i < NBLK; i++) {
        const float* Wq = twt + (0*NBLK + i) * DD2;  const float* bq = tqb + i * DDIM;
        const float* Wk = twt + (1*NBLK + i) * DD2;  const float* bk = tkb + i * DDIM;
        const float* Wv = twt + (2*NBLK + i) * DD2;  const float* bv = tvb + i * DDIM;
        const float* Wo = twt + (3*NBLK + i) * DD2;  const float* bo = tob + i * DDIM;
        const float* W1 = f1t + (long long)i * DDIM * DFF;  const float* b1 = tf1b + i * DFF;
        const float* W2 = f2t + (long long)i * DFF * DDIM;  const float* b2 = tf2b + i * DDIM;
        const float* ng = tng + i * DDIM;                   const float* nb = tnb + i * DDIM;

        tcg(y, Wq, q, bq, nullptr, M, DDIM, DDIM, DDIM, DDIM, DDIM, 1.f, false, 1, 1, 0,0,0,0,0,0);
        tcg(y, Wk, k, bk, nullptr, M, DDIM, DDIM, DDIM, DDIM, DDIM, 1.f, false, 1, 1, 0,0,0,0,0,0);
        tcg(y, Wv, v, bv, nullptr, M, DDIM, DDIM, DDIM, DDIM, DDIM, 1.f, false, 1, 1, 0,0,0,0,0,0);
        transpose_kernel<<<dim3(16,32,BB), tb>>>(v, vt, LL, DDIM);

        tcg(q, k, s, nullptr, nullptr, LL, LL, DDIM, DDIM, DDIM, LL, 1.f, false,
            BB, 1, LD, 0, LD, 0, LLs, 0);
        softmax_kernel<<<BB * LL, 256>>>(s);

        // probs @ v : B = vt[b]  [D, L]
        tcg(s, vt, t, nullptr, nullptr, LL, DDIM, LL, LL, LL, DDIM, 1.f, false,
            BB, 1, LLs, 0, LD, 0, LD, 0);

        permute_kernel<<<(BLD + 255) / 256, 256>>>(t, t2);
        tcg(t2, Wo, y, bo, y, M, DDIM, DDIM, DDIM, DDIM, DDIM, 1.f, false, 1, 1, 0,0,0,0,0,0);

        ln_kernel<<<M, 128>>>(y, nullptr, ng, nb, xn);
        tcg(xn, W1, h, b1, nullptr, M, DFF, DDIM, DDIM, DDIM, DFF, 1.f, true, 1, 1, 0,0,0,0,0,0);
        tcg(h,  W2, y, b2, y,       M, DDIM, DFF,  DFF,  DFF,  DDIM, 1.f, false, 1, 1, 0,0,0,0,0,0);
    }

    ln_kernel<<<M, 128>>>(x, y, n2g, n2b, out_ln);
}

// round 6
// speedup vs baseline: 5.8904x; 1.0702x over previous
#include <cuda_runtime.h>
#include <cuda_fp16.h>
#include <cstdint>

#define BB   8
#define LL   1024
#define DDIM 512
#define HH   8
#define EE   64
#define DFF  2048
#define NBLK 3
#define BLD  (BB*LL*DDIM)
#define BLL  (BB*LL*LL)
#define BHLL (BB*HH*LL*LL)
#define BLDF (BB*LL*DFF)
#define DD2  (DDIM*DDIM)

// ---------------- scratch ----------------
__device__ float g_q[BLD];
__device__ float g_k[BLD];
__device__ float g_v[BLD];
__device__ float g_vt[BLD];
__device__ float g_t[BLD];
__device__ float g_t2[BLD];
__device__ float g_x[BLD];
__device__ float g_y[BLD];
__device__ float g_xn[BLD];
__device__ float g_s[BLL];
__device__ float g_h[BLDF];
__device__ float g_A[BHLL];
__device__ float g_awt[4*DD2];
__device__ float g_twt[4*NBLK*DD2];
__device__ float g_f1t[NBLK*DDIM*DFF];
__device__ float g_f2t[NBLK*DFF*DDIM];

// ---------------- helpers ----------------
__device__ __forceinline__ void mma16816(float* d, const uint32_t* a, uint32_t b0, uint32_t b1) {
    asm volatile(
        "mma.sync.aligned.m16n8k16.row.col.f32.f16.f16.f32 "
        "{%0,%1,%2,%3}, {%4,%5,%6,%7}, {%8,%9}, {%0,%1,%2,%3};"
        : "+f"(d[0]), "+f"(d[1]), "+f"(d[2]), "+f"(d[3])
        : "r"(a[0]), "r"(a[1]), "r"(a[2]), "r"(a[3]), "r"(b0), "r"(b1));
}
__device__ __forceinline__ void ldm_x4(uint32_t* r, uint32_t addr) {
    asm volatile("ldmatrix.sync.aligned.m8n8.x4.shared.b16 {%0,%1,%2,%3}, [%4];"
        : "=r"(r[0]), "=r"(r[1]), "=r"(r[2]), "=r"(r[3]) : "r"(addr));
}
__device__ __forceinline__ void split4(float4 v, uint2& hi, uint2& lo) {
    __half2 h01 = __floats2half2_rn(v.x, v.y);
    __half2 h23 = __floats2half2_rn(v.z, v.w);
    float2 f01 = __half22float2(h01);
    float2 f23 = __half22float2(h23);
    __half2 l01 = __floats2half2_rn(v.x - f01.x, v.y - f01.y);
    __half2 l23 = __floats2half2_rn(v.z - f23.x, v.w - f23.y);
    hi.x = *(uint32_t*)&h01; hi.y = *(uint32_t*)&h23;
    lo.x = *(uint32_t*)&l01; lo.y = *(uint32_t*)&l23;
}

// ============ fp16 hi/lo split tensor GEMM (ldmatrix fragments) ============
// C[M,N] = alpha*A[M,K]@B[N,K]^T (+bias)(+res)(relu); fp32-grade via h*h+h*l+l*h.
// CTA 128xBN, BK=32, 512 threads = 16 warps (4x4), warp tile 32x(BN/4).
template<int BN, bool RELU>
__global__ void __launch_bounds__(512) hgemm(
    const float* __restrict__ A, const float* __restrict__ B, float* __restrict__ C,
    const float* __restrict__ bias, const float* __restrict__ res,
    int K, int lda, int ldb, int ldc, float alpha, int inner,
    long long sAo, long long sAi, long long sBo, long long sBi,
    long long sCo, long long sCi)
{
    constexpr int LDS_ = 40;                    // BK=32 halves + 8 pad
    constexpr int ABYT = 128 * LDS_;            // halves
    constexpr int BBYT = BN * LDS_;
    constexpr int STAGE = 2 * ABYT + 2 * BBYT;  // Ah,Al,Bh,Bl
    constexpr int NA   = BN / 32;               // 8-wide n atoms per warp tile
    constexpr int NA4  = 2;
    constexpr int NB4  = BN / 64;

    extern __shared__ __half smb[];
    const uint32_t smb0 = (uint32_t)__cvta_generic_to_shared(smb);

    int z  = blockIdx.z;
    int zo = z / inner;
    int zi = z - zo * inner;
    A += zo * sAo + zi * sAi;
    B += zo * sBo + zi * sBi;
    long long coff = zo * sCo + zi * sCi;
    C += coff;
    if (res) res += coff;

    const int tid  = threadIdx.x;
    const int wid  = tid >> 5, lane = tid & 31;
    const int g    = lane >> 2, t4 = lane & 3;
    const int row0 = blockIdx.y * 128, col0 = blockIdx.x * BN;
    const int arow = (wid & 3) * 32;
    const int brow = (wid >> 2) * (BN / 4);

    // ldmatrix address invariants
    const int a_r    = arow + (lane & 15);
    const int a_koff = (lane >> 4) * 8;
    const int b_mat  = lane >> 3, b_row = lane & 7;
    const int b_n    = brow + (b_mat >> 1) * 8 + b_row;
    const int b_koff = (b_mat & 1) * 8;

    float acc[2][NA][4];
    #pragma unroll
    for (int i = 0; i < 2; i++)
        #pragma unroll
        for (int j = 0; j < NA; j++)
            #pragma unroll
            for (int e = 0; e < 4; e++) acc[i][j][e] = 0.f;

    float4 av[NA4], bv[NB4];

    auto load_chunk = [&](int c) {
        const int k0 = c * 32;
        #pragma unroll
        for (int i = 0; i < NA4; i++) {
            int f = tid + i * 512; int r = f >> 3, kq = f & 7;
            av[i] = *(const float4*)(A + (size_t)(row0 + r) * lda + k0 + kq * 4);
        }
        #pragma unroll
        for (int i = 0; i < NB4; i++) {
            int f = tid + i * 512; int r = f >> 3, kq = f & 7;
            bv[i] = *(const float4*)(B + (size_t)(col0 + r) * ldb + k0 + kq * 4);
        }
    };
    auto store_chunk = [&](int buf) {
        __half* pAh = smb + buf * STAGE;
        __half* pAl = pAh + ABYT;
        __half* pBh = pAl + ABYT;
        __half* pBl = pBh + BBYT;
        #pragma unroll
        for (int i = 0; i < NA4; i++) {
            int f = tid + i * 512; int r = f >> 3, kq = f & 7;
            uint2 h, l; split4(av[i], h, l);
            *(uint2*)&pAh[r * LDS_ + kq * 4] = h;
            *(uint2*)&pAl[r * LDS_ + kq * 4] = l;
        }
        #pragma unroll
        for (int i = 0; i < NB4; i++) {
            int f = tid + i * 512; int r = f >> 3, kq = f & 7;
            uint2 h, l; split4(bv[i], h, l);
            *(uint2*)&pBh[r * LDS_ + kq * 4] = h;
            *(uint2*)&pBl[r * LDS_ + kq * 4] = l;
        }
    };

    const int NC = K >> 5;
    load_chunk(0);
    store_chunk(0);
    __syncthreads();

    for (int c = 0; c < NC; c++) {
        const int buf = c & 1;
        if (c + 1 < NC) load_chunk(c + 1);

        const uint32_t oAh = smb0 + (uint32_t)(buf * STAGE) * 2u;
        const uint32_t oAl = oAh + ABYT * 2u;
        const uint32_t oBh = oAl + ABYT * 2u;
        const uint32_t oBl = oBh + BBYT * 2u;

        #pragma unroll
        for (int ka = 0; ka < 2; ka++) {
            uint32_t ah[2][4], al[2][4], bh[NA][2], bl[NA][2];
            #pragma unroll
            for (int ma = 0; ma < 2; ma++) {
                uint32_t off = (uint32_t)((a_r + ma * 16) * LDS_ + ka * 16 + a_koff) * 2u;
                ldm_x4(ah[ma], oAh + off);
                ldm_x4(al[ma], oAl + off);
            }
            #pragma unroll
            for (int p = 0; p < NA / 2; p++) {
                uint32_t off = (uint32_t)((b_n + p * 16) * LDS_ + ka * 16 + b_koff) * 2u;
                uint32_t tm[4];
                ldm_x4(tm, oBh + off);
                bh[p * 2][0] = tm[0]; bh[p * 2][1] = tm[1];
                bh[p * 2 + 1][0] = tm[2]; bh[p * 2 + 1][1] = tm[3];
                ldm_x4(tm, oBl + off);
                bl[p * 2][0] = tm[0]; bl[p * 2][1] = tm[1];
                bl[p * 2 + 1][0] = tm[2]; bl[p * 2 + 1][1] = tm[3];
            }
            #pragma unroll
            for (int na = 0; na < NA; na++) {
                #pragma unroll
                for (int ma = 0; ma < 2; ma++) {
                    mma16816(acc[ma][na], ah[ma], bh[na][0], bh[na][1]);
                    mma16816(acc[ma][na], ah[ma], bl[na][0], bl[na][1]);
                    mma16816(acc[ma][na], al[ma], bh[na][0], bh[na][1]);
                }
            }
        }
        if (c + 1 < NC) store_chunk(buf ^ 1);
        __syncthreads();
    }

    // ---- epilogue ----
    #pragma unroll
    for (int ma = 0; ma < 2; ma++) {
        #pragma unroll
        for (int na = 0; na < NA; na++) {
            int r_ = row0 + arow + ma * 16 + g;
            int n_ = col0 + brow + na * 8 + t4 * 2;
            float2 bb = bias ? *(const float2*)&bias[n_] : make_float2(0.f, 0.f);
            #pragma unroll
            for (int half_ = 0; half_ < 2; half_++) {
                int m = r_ + half_ * 8;
                float2 v;
                v.x = acc[ma][na][half_ * 2 + 0] * alpha + bb.x;
                v.y = acc[ma][na][half_ * 2 + 1] * alpha + bb.y;
                if (res) {
                    float2 rr = *(const float2*)&res[(size_t)m * ldc + n_];
                    v.x += rr.x; v.y += rr.y;
                }
                if (RELU) { v.x = fmaxf(v.x, 0.f); v.y = fmaxf(v.y, 0.f); }
                *(float2*)&C[(size_t)m * ldc + n_] = v;
            }
        }
    }
}

// ---------------- tiled transpose: out[C,R] = in[R,C]^T, batched ----------------
__global__ void transpose_kernel(const float* __restrict__ in, float* __restrict__ out, int R, int C)
{
    __shared__ float tile[32][33];
    size_t bo = (size_t)blockIdx.z * R * C;
    int c0 = blockIdx.x * 32, r0 = blockIdx.y * 32;
    int tx = threadIdx.x, ty = threadIdx.y;
    #pragma unroll
    for (int j = 0; j < 4; j++)
        tile[ty + j * 8][tx] = in[bo + (size_t)(r0 + ty + j * 8) * C + c0 + tx];
    __syncthreads();
    #pragma unroll
    for (int j = 0; j < 4; j++)
        out[bo + (size_t)(c0 + ty + j * 8) * R + r0 + tx] = tile[tx][ty + j * 8];
}

// ---------------- softmax (rows of 1024) ----------------
__global__ void softmax_kernel(float* __restrict__ P)
{
    long long base = (long long)blockIdx.x * 1024;
    int tid = threadIdx.x;
    __shared__ float red[256];
    float4 vv = *(const float4*)&P[base + tid * 4];
    float v[4] = {vv.x, vv.y, vv.z, vv.w};
    float mx = fmaxf(fmaxf(v[0], v[1]), fmaxf(v[2], v[3]));
    red[tid] = mx; __syncthreads();
    for (int s = 128; s > 0; s >>= 1) { if (tid < s) red[tid] = fmaxf(red[tid], red[tid + s]); __syncthreads(); }
    mx = red[0]; __syncthreads();
    float sum = 0.f;
    #pragma unroll
    for (int i = 0; i < 4; i++) { v[i] = __expf(v[i] - mx); sum += v[i]; }
    red[tid] = sum; __syncthreads();
    for (int s = 128; s > 0; s >>= 1) { if (tid < s) red[tid] += red[tid + s]; __syncthreads(); }
    float inv = 1.f / red[0];
    vv.x = v[0] * inv; vv.y = v[1] * inv; vv.z = v[2] * inv; vv.w = v[3] * inv;
    *(float4*)&P[base + tid * 4] = vv;
}

// ---------------- layernorm over D=512 ----------------
__global__ void ln_kernel(const float* __restrict__ a, const float* __restrict__ b,
                          const float* __restrict__ g, const float* __restrict__ beta,
                          float* __restrict__ out)
{
    long long base = (long long)blockIdx.x * 512;
    int tid = threadIdx.x;   // 128
    __shared__ float red[128];
    float4 xv = *(const float4*)&a[base + tid * 4];
    if (b) {
        float4 bv = *(const float4*)&b[base + tid * 4];
        xv.x += bv.x; xv.y += bv.y; xv.z += bv.z; xv.w += bv.w;
    }
    red[tid] = xv.x + xv.y + xv.z + xv.w; __syncthreads();
    for (int s = 64; s > 0; s >>= 1) { if (tid < s) red[tid] += red[tid + s]; __syncthreads(); }
    float mean = red[0] * (1.f / 512.f);
    __syncthreads();
    float d0 = xv.x - mean, d1 = xv.y - mean, d2 = xv.z - mean, d3 = xv.w - mean;
    red[tid] = d0 * d0 + d1 * d1 + d2 * d2 + d3 * d3; __syncthreads();
    for (int s = 64; s > 0; s >>= 1) { if (tid < s) red[tid] += red[tid + s]; __syncthreads(); }
    float rstd = rsqrtf(red[0] * (1.f / 512.f) + 1e-5f);
    float4 gv = *(const float4*)&g[tid * 4];
    float4 bt = *(const float4*)&beta[tid * 4];
    float4 ov;
    ov.x = d0 * rstd * gv.x + bt.x;
    ov.y = d1 * rstd * gv.y + bt.y;
    ov.z = d2 * rstd * gv.z + bt.z;
    ov.w = d3 * rstd * gv.w + bt.w;
    *(float4*)&out[base + tid * 4] = ov;
}

// ---------------- temporal "transpose-reshape" ----------------
__global__ void permute_kernel(const float* __restrict__ in, float* __restrict__ out)
{
    long long i = (long long)blockIdx.x * 256 + threadIdx.x;
    if (i >= (long long)BLD) return;
    long long b = i / (LL * DDIM);
    int f = (int)(i - b * (LL * DDIM));
    out[i] = in[b * (LL * DDIM) + (long long)(f & (LL - 1)) * DDIM + (f >> 10)];
}

// ---------------- host dispatch ----------------
static void tcg(const float* A, const float* B, float* C,
                const float* bias, const float* res,
                int M, int N, int K, int lda, int ldb, int ldc,
                float alpha, bool relu, int batch, int inner,
                long long sAo, long long sAi, long long sBo, long long sBi,
                long long sCo, long long sCi)
{
    if (N % 128 == 0) {
        dim3 g(N / 128, M / 128, batch);
        size_t sm = 2ull * (2 * 128 * 40 + 2 * 128 * 40) * sizeof(__half);  // 81920
        if (relu) {
            cudaFuncSetAttribute(hgemm<128, true >, cudaFuncAttributeMaxDynamicSharedMemorySize, (int)sm);
            hgemm<128, true ><<<g, 512, sm>>>(A, B, C, bias, res, K, lda, ldb, ldc, alpha, inner, sAo, sAi, sBo, sBi, sCo, sCi);
        } else {
            cudaFuncSetAttribute(hgemm<128, false>, cudaFuncAttributeMaxDynamicSharedMemorySize, (int)sm);
            hgemm<128, false><<<g, 512, sm>>>(A, B, C, bias, res, K, lda, ldb, ldc, alpha, inner, sAo, sAi, sBo, sBi, sCo, sCi);
        }
    } else { // N == 64
        dim3 g(N / 64, M / 128, batch);
        size_t sm = 2ull * (2 * 128 * 40 + 2 * 64 * 40) * sizeof(__half);   // 61440
        cudaFuncSetAttribute(hgemm<64, false>, cudaFuncAttributeMaxDynamicSharedMemorySize, (int)sm);
        hgemm<64, false><<<g, 512, sm>>>(A, B, C, bias, res, K, lda, ldb, ldc, alpha, inner, sAo, sAi, sBo, sBi, sCo, sCi);
    }
}

extern "C" void kernel_launch(void* const* d_in, const int* in_sizes, int n_in,
                              void* d_out, int out_size)
{
    const float* x0   = (const float*)d_in[0];
    const float* aw_q = (const float*)d_in[1];   const float* ab_q = (const float*)d_in[2];
    const float* aw_k = (const float*)d_in[3];   const float* ab_k = (const float*)d_in[4];
    const float* aw_v = (const float*)d_in[5];   const float* ab_v = (const float*)d_in[6];
    const float* aw_o = (const float*)d_in[7];   const float* ab_o = (const float*)d_in[8];
    const float* n1g  = (const float*)d_in[9];   const float* n1b  = (const float*)d_in[10];
    const float* n2g  = (const float*)d_in[11];  const float* n2b  = (const float*)d_in[12];
    const float* tqw  = (const float*)d_in[13];  const float* tqb  = (const float*)d_in[14];
    const float* tkw  = (const float*)d_in[15];  const float* tkb  = (const float*)d_in[16];
    const float* tvw  = (const float*)d_in[17];  const float* tvb  = (const float*)d_in[18];
    const float* tow  = (const float*)d_in[19];  const float* tob  = (const float*)d_in[20];
    const float* tf1w = (const float*)d_in[21];  const float* tf1b = (const float*)d_in[22];
    const float* tf2w = (const float*)d_in[23];  const float* tf2b = (const float*)d_in[24];
    const float* tng  = (const float*)d_in[25];  const float* tnb  = (const float*)d_in[26];

    float *q,*k,*v,*vt,*t,*t2,*x,*y,*xn,*s,*h,*Afb,*awt,*twt,*f1t,*f2t;
    cudaGetSymbolAddress((void**)&q,  g_q);
    cudaGetSymbolAddress((void**)&k,  g_k);
    cudaGetSymbolAddress((void**)&v,  g_v);
    cudaGetSymbolAddress((void**)&vt, g_vt);
    cudaGetSymbolAddress((void**)&t,  g_t);
    cudaGetSymbolAddress((void**)&t2, g_t2);
    cudaGetSymbolAddress((void**)&x,  g_x);
    cudaGetSymbolAddress((void**)&y,  g_y);
    cudaGetSymbolAddress((void**)&xn, g_xn);
    cudaGetSymbolAddress((void**)&s,  g_s);
    cudaGetSymbolAddress((void**)&h,  g_h);
    cudaGetSymbolAddress((void**)&Afb, g_A);
    cudaGetSymbolAddress((void**)&awt, g_awt);
    cudaGetSymbolAddress((void**)&twt, g_twt);
    cudaGetSymbolAddress((void**)&f1t, g_f1t);
    cudaGetSymbolAddress((void**)&f2t, g_f2t);

    float* out_ln = (float*)d_out;
    float* Ap = (out_size >= (BLD + BHLL)) ? ((float*)d_out + BLD) : Afb;

    const int M = BB * LL;
    const long long LD  = (long long)LL * DDIM;
    const long long LLs = (long long)LL * LL;
    dim3 tb(32, 8);

    // ---- transpose all weights to [N,K] ----
    transpose_kernel<<<dim3(16,16,1), tb>>>(aw_q, awt + 0*DD2, DDIM, DDIM);
    transpose_kernel<<<dim3(16,16,1), tb>>>(aw_k, awt + 1*DD2, DDIM, DDIM);
    transpose_kernel<<<dim3(16,16,1), tb>>>(aw_v, awt + 2*DD2, DDIM, DDIM);
    transpose_kernel<<<dim3(16,16,1), tb>>>(aw_o, awt + 3*DD2, DDIM, DDIM);
    transpose_kernel<<<dim3(16,16,NBLK), tb>>>(tqw, twt + 0*NBLK*DD2, DDIM, DDIM);
    transpose_kernel<<<dim3(16,16,NBLK), tb>>>(tkw, twt + 1*NBLK*DD2, DDIM, DDIM);
    transpose_kernel<<<dim3(16,16,NBLK), tb>>>(tvw, twt + 2*NBLK*DD2, DDIM, DDIM);
    transpose_kernel<<<dim3(16,16,NBLK), tb>>>(tow, twt + 3*NBLK*DD2, DDIM, DDIM);
    transpose_kernel<<<dim3(64,16,NBLK), tb>>>(tf1w, f1t, DDIM, DFF);
    transpose_kernel<<<dim3(16,64,NBLK), tb>>>(tf2w, f2t, DFF, DDIM);

    // ---- outer MHA ----
    tcg(x0, awt + 0*DD2, q, ab_q, nullptr, M, DDIM, DDIM, DDIM, DDIM, DDIM, 1.f, false, 1, 1, 0,0,0,0,0,0);
    tcg(x0, awt + 1*DD2, k, ab_k, nullptr, M, DDIM, DDIM, DDIM, DDIM, DDIM, 1.f, false, 1, 1, 0,0,0,0,0,0);
    tcg(x0, awt + 2*DD2, v, ab_v, nullptr, M, DDIM, DDIM, DDIM, DDIM, DDIM, 1.f, false, 1, 1, 0,0,0,0,0,0);
    transpose_kernel<<<dim3(16,32,BB), tb>>>(v, vt, LL, DDIM);   // vt[b] = v[b]^T  [D,L]

    // scores: q_h @ k_h^T / 8
    tcg(q, k, Ap, nullptr, nullptr, LL, LL, EE, DDIM, DDIM, LL, 0.125f, false,
        BB * HH, HH, LD, EE, LD, EE, (long long)HH * LLs, LLs);
    softmax_kernel<<<BB * HH * LL, 256>>>(Ap);

    // out = A @ v_h : B = vt head slice [64, L]
    tcg(Ap, vt, t, nullptr, nullptr, LL, EE, LL, LL, LL, DDIM, 1.f, false,
        BB * HH, HH, (long long)HH * LLs, LLs, LD, (long long)EE * LL, LD, EE);

    tcg(t, awt + 3*DD2, t2, ab_o, x0, M, DDIM, DDIM, DDIM, DDIM, DDIM, 1.f, false, 1, 1, 0,0,0,0,0,0);
    ln_kernel<<<M, 128>>>(t2, nullptr, n1g, n1b, x);
    cudaMemcpyAsync(y, x, (size_t)BLD * sizeof(float), cudaMemcpyDeviceToDevice, 0);

    // ---- temporal blocks ----
    for (int i = 0; i < NBLK; i++) {
        const float* Wq = twt + (0*NBLK + i) * DD2;  const float* bq = tqb + i * DDIM;
        const float* Wk = twt + (1*NBLK + i) * DD2;  const float* bk = tkb + i * DDIM;
        const float* Wv = twt + (2*NBLK + i) * DD2;  const float* bv = tvb + i * DDIM;
        const float* Wo = twt + (3*NBLK + i) * DD2;  const float* bo = tob + i * DDIM;
        const float* W1 = f1t + (long long)i * DDIM * DFF;  const float* b1 = tf1b + i * DFF;
        const float* W2 = f2t + (long long)i * DFF * DDIM;  const float* b2 = tf2b + i * DDIM;
        const float* ng = tng + i * DDIM;                   const float* nb = tnb + i * DDIM;

        tcg(y, Wq, q, bq, nullptr, M, DDIM, DDIM, DDIM, DDIM, DDIM, 1.f, false, 1, 1, 0,0,0,0,0,0);
        tcg(y, Wk, k, bk, nullptr, M, DDIM, DDIM, DDIM, DDIM, DDIM, 1.f, false, 1, 1, 0,0,0,0,0,0);
        tcg(y, Wv, v, bv, nullptr, M, DDIM, DDIM, DDIM, DDIM, DDIM, 1.f, false, 1, 1, 0,0,0,0,0,0);
        transpose_kernel<<<dim3(16,32,BB), tb>>>(v, vt, LL, DDIM);

        tcg(q, k, s, nullptr, nullptr, LL, LL, DDIM, DDIM, DDIM, LL, 1.f, false,
            BB, 1, LD, 0, LD, 0, LLs, 0);
        softmax_kernel<<<BB * LL, 256>>>(s);

        // probs @ v : B = vt[b]  [D, L]
        tcg(s, vt, t, nullptr, nullptr, LL, DDIM, LL, LL, LL, DDIM, 1.f, false,
            BB, 1, LLs, 0, LD, 0, LD, 0);

        permute_kernel<<<(BLD + 255) / 256, 256>>>(t, t2);
        tcg(t2, Wo, y, bo, y, M, DDIM, DDIM, DDIM, DDIM, DDIM, 1.f, false, 1, 1, 0,0,0,0,0,0);

        ln_kernel<<<M, 128>>>(y, nullptr, ng, nb, xn);
        tcg(xn, W1, h, b1, nullptr, M, DFF, DDIM, DDIM, DDIM, DFF, 1.f, true, 1, 1, 0,0,0,0,0,0);
        tcg(h,  W2, y, b2, y,       M, DDIM, DFF,  DFF,  DFF,  DDIM, 1.f, false, 1, 1, 0,0,0,0,0,0);
    }

    ln_kernel<<<M, 128>>>(x, y, n2g, n2b, out_ln);
}